// round 8
// baseline (speedup 1.0000x reference)
#include <cuda_runtime.h>
#include <cuda_bf16.h>
#include <math.h>
#include <stdint.h>

// ---------------------------------------------------------------------------
// Problem constants
// ---------------------------------------------------------------------------
#define BATCH     2
#define SEQ       8192
#define HID       1024
#define NHEADS    16
#define HDIM      64
#define KWIN      7
#define ATT_SCALE 0.125f
#define M_ROWS    (BATCH * SEQ)     // 16384

// ---------------------------------------------------------------------------
// Scratch (__device__ globals: allowed, no runtime allocation)
// ---------------------------------------------------------------------------
__device__ float g_q[(size_t)M_ROWS * HID];
__device__ float g_k[(size_t)M_ROWS * HID];
__device__ float g_v[(size_t)M_ROWS * HID];
__device__ __nv_bfloat16 g_a_hi[(size_t)M_ROWS * HID];
__device__ __nv_bfloat16 g_a_lo[(size_t)M_ROWS * HID];
__device__ __nv_bfloat16 g_o_hi[(size_t)M_ROWS * HID];   // attention out hi
__device__ __nv_bfloat16 g_o_lo[(size_t)M_ROWS * HID];   // attention out lo
__device__ __nv_bfloat16 g_w_hi[(size_t)4 * HID * HID];  // transposed [n][k]
__device__ __nv_bfloat16 g_w_lo[(size_t)4 * HID * HID];

// ---------------------------------------------------------------------------
// PTX helpers (base sm_103 target — NO 'a'-gated features)
// ---------------------------------------------------------------------------
__device__ __forceinline__ uint32_t smem_u32(const void* p) {
    uint32_t a;
    asm("{ .reg .u64 t; cvta.to.shared.u64 t, %1; cvt.u32.u64 %0, t; }"
        : "=r"(a) : "l"(p));
    return a;
}
__device__ __forceinline__ void cp16(uint32_t s, const void* g) {
    asm volatile("cp.async.cg.shared.global [%0], [%1], 16;"
                 :: "r"(s), "l"(g));
}
__device__ __forceinline__ void ldsm_x4(uint32_t* r, uint32_t addr) {
    asm volatile("ldmatrix.sync.aligned.m8n8.x4.shared.b16 {%0,%1,%2,%3}, [%4];"
                 : "=r"(r[0]), "=r"(r[1]), "=r"(r[2]), "=r"(r[3]) : "r"(addr));
}
__device__ __forceinline__ void mma16816(float* d, const uint32_t* a,
                                         const uint32_t* b) {
    asm volatile(
        "mma.sync.aligned.m16n8k16.row.col.f32.bf16.bf16.f32 "
        "{%0,%1,%2,%3}, {%4,%5,%6,%7}, {%8,%9}, {%0,%1,%2,%3};"
        : "+f"(d[0]), "+f"(d[1]), "+f"(d[2]), "+f"(d[3])
        : "r"(a[0]), "r"(a[1]), "r"(a[2]), "r"(a[3]), "r"(b[0]), "r"(b[1]));
}

// ---------------------------------------------------------------------------
// GEMM config: 128x256 CTA tile, BK=32, 3-stage cp.async ring, 512 threads
// ---------------------------------------------------------------------------
#define PITCH   80                      // bytes per 32-elem bf16 row (64+16 pad)
#define TILE_A  (128 * PITCH)           // 10240
#define TILE_B  (256 * PITCH)           // 20480
#define OFF_AL  TILE_A                  // 10240
#define OFF_BH  (2 * TILE_A)            // 20480
#define OFF_BL  (2 * TILE_A + TILE_B)   // 40960
#define BUFB    (2 * TILE_A + 2 * TILE_B)   // 61440 per stage
#define NSTAGE  3
#define SMEMB   (NSTAGE * BUFB)         // 184320

__device__ __forceinline__ void load_chunk(
    uint32_t base, int tid, int k0, int m0, int n0,
    const __nv_bfloat16* __restrict__ Ah, const __nv_bfloat16* __restrict__ Al,
    const __nv_bfloat16* __restrict__ Bh, const __nv_bfloat16* __restrict__ Bl)
{
    {   // A hi/lo: 128 rows x 64B, 512 threads -> 1 cp16 each per tile
        int row = tid >> 2, c = tid & 3;
        uint32_t so = (uint32_t)(row * PITCH + c * 16);
        size_t go = (size_t)(m0 + row) * HID + k0 + c * 8;
        cp16(base + so,          Ah + go);
        cp16(base + OFF_AL + so, Al + go);
    }
#pragma unroll
    for (int r = 0; r < 2; r++) {   // B hi/lo: 256 rows x 64B
        int idx = tid + r * 512;
        int row = idx >> 2, c = idx & 3;
        uint32_t so = (uint32_t)(row * PITCH + c * 16);
        size_t go = (size_t)(n0 + row) * HID + k0 + c * 8;
        cp16(base + OFF_BH + so, Bh + go);
        cp16(base + OFF_BL + so, Bl + go);
    }
    asm volatile("cp.async.commit_group;" ::: "memory");
}

// C[m][n] = sum_k A[m][k]*Bt[n][k] + bias[n], 3-pass bf16 split HMMA.
// grid.x: (matrix_within_launch << 2) | n_tile;  grid.y: m_tile
__global__ void __launch_bounds__(512, 1)
gemm_mma(const __nv_bfloat16* __restrict__ Ah, const __nv_bfloat16* __restrict__ Al,
         const __nv_bfloat16* __restrict__ Wh, const __nv_bfloat16* __restrict__ Wl,
         int mat_base,
         const float* __restrict__ bias0, const float* __restrict__ bias1,
         const float* __restrict__ bias2,
         float* __restrict__ c0, float* __restrict__ c1, float* __restrict__ c2)
{
    extern __shared__ char smem[];
    const uint32_t sb = smem_u32(smem);
    const int tid  = threadIdx.x;
    const int lane = tid & 31;
    const int wid  = tid >> 5;          // 0..15
    const int wm   = wid >> 3;          // 0..1 -> 64-row slab
    const int wn   = wid & 7;           // 0..7 -> 32-col slab
    const int mi_  = blockIdx.x >> 2;   // matrix within launch
    const int n0   = (blockIdx.x & 3) * 256;
    const int m0   = blockIdx.y * 128;

    const __nv_bfloat16* Bh = Wh + (size_t)(mat_base + mi_) * HID * HID;
    const __nv_bfloat16* Bl = Wl + (size_t)(mat_base + mi_) * HID * HID;
    const float* bias = (mi_ == 0) ? bias0 : ((mi_ == 1) ? bias1 : bias2);
    float* C = (mi_ == 0) ? c0 : ((mi_ == 1) ? c1 : c2);

    float acc[4][4][4];
#pragma unroll
    for (int i = 0; i < 4; i++)
#pragma unroll
        for (int j = 0; j < 4; j++)
#pragma unroll
            for (int r = 0; r < 4; r++) acc[i][j][r] = 0.0f;

    // prologue: stages 0,1
    load_chunk(sb,        tid, 0,  m0, n0, Ah, Al, Bh, Bl);
    load_chunk(sb + BUFB, tid, 32, m0, n0, Ah, Al, Bh, Bl);

    // per-thread ldmatrix source offsets (identical to verified R6/R7 layout)
    const int mrow = lane >> 3;
    const int jrow = lane & 7;
    const uint32_t a_off = (uint32_t)((wm * 64 + (mrow & 1) * 8 + jrow) * PITCH
                                      + (mrow >> 1) * 16);
    const uint32_t b_off = (uint32_t)((wn * 32 + (mrow >> 1) * 8 + jrow) * PITCH
                                      + (mrow & 1) * 16) + OFF_BH;

    const int NCHUNK = HID / 32;        // 32
    uint32_t stage_base[NSTAGE] = {sb, sb + BUFB, sb + 2 * BUFB};
    int st = 0;                         // stage of current chunk

    for (int ck = 0; ck < NCHUNK; ck++) {
        if (ck < NCHUNK - 2) asm volatile("cp.async.wait_group 1;" ::: "memory");
        else                 asm volatile("cp.async.wait_group 0;" ::: "memory");
        __syncthreads();   // chunk ck visible; all warps done with chunk ck-1

        // prefetch chunk ck+2 into the stage freed at iter ck-1
        if (ck + 2 < NCHUNK) {
            int ls = st + 2; if (ls >= NSTAGE) ls -= NSTAGE;
            load_chunk(stage_base[ls], tid, (ck + 2) * 32, m0, n0,
                       Ah, Al, Bh, Bl);
        }

        const uint32_t base = stage_base[st];
#pragma unroll
        for (int ks = 0; ks < 2; ks++) {
            const uint32_t kb = ks * 32;
            uint32_t bh[2][4], bl[2][4];
#pragma unroll
            for (int nj = 0; nj < 2; nj++) {
                uint32_t bd = base + b_off + nj * 16 * PITCH + kb;
                ldsm_x4(bh[nj], bd);
                ldsm_x4(bl[nj], bd + TILE_B);   // OFF_BL - OFF_BH
            }
            // process M-slabs in pairs: pass-major ordering gives each acc
            // tile a reuse distance of 8 independent HMMAs (covers latency)
#pragma unroll
            for (int mp = 0; mp < 2; mp++) {
                uint32_t ahf[2][4], alf[2][4];
#pragma unroll
                for (int u = 0; u < 2; u++) {
                    uint32_t ad = base + a_off + (mp * 2 + u) * 16 * PITCH + kb;
                    ldsm_x4(ahf[u], ad);
                    ldsm_x4(alf[u], ad + OFF_AL);
                }
                // pass 0: Ah*Bh  (8 independent acc tiles)
#pragma unroll
                for (int u = 0; u < 2; u++)
#pragma unroll
                    for (int ni = 0; ni < 4; ni++)
                        mma16816(acc[mp * 2 + u][ni], ahf[u],
                                 &bh[ni >> 1][(ni & 1) * 2]);
                // pass 1: Ah*Bl
#pragma unroll
                for (int u = 0; u < 2; u++)
#pragma unroll
                    for (int ni = 0; ni < 4; ni++)
                        mma16816(acc[mp * 2 + u][ni], ahf[u],
                                 &bl[ni >> 1][(ni & 1) * 2]);
                // pass 2: Al*Bh
#pragma unroll
                for (int u = 0; u < 2; u++)
#pragma unroll
                    for (int ni = 0; ni < 4; ni++)
                        mma16816(acc[mp * 2 + u][ni], alf[u],
                                 &bh[ni >> 1][(ni & 1) * 2]);
            }
        }
        if (++st == NSTAGE) st = 0;
    }

    // epilogue: fragment layout -> C, add bias
    const int grp = lane >> 2, t4 = lane & 3;
#pragma unroll
    for (int ni = 0; ni < 4; ni++) {
        const int col = n0 + wn * 32 + ni * 8 + t4 * 2;
        const float bv0 = bias[col], bv1 = bias[col + 1];
#pragma unroll
        for (int mi = 0; mi < 4; mi++) {
            const int r0 = m0 + wm * 64 + mi * 16 + grp;
            *(float2*)(C + (size_t)r0 * HID + col) =
                make_float2(acc[mi][ni][0] + bv0, acc[mi][ni][1] + bv1);
            *(float2*)(C + (size_t)(r0 + 8) * HID + col) =
                make_float2(acc[mi][ni][2] + bv0, acc[mi][ni][3] + bv1);
        }
    }
}

// ---------------------------------------------------------------------------
// Decompose fp32 -> bf16 hi + bf16 lo (elementwise)
// ---------------------------------------------------------------------------
__global__ void __launch_bounds__(256)
decompose_act(const float* __restrict__ x,
              __nv_bfloat16* __restrict__ hi, __nv_bfloat16* __restrict__ lo)
{
    size_t i = ((size_t)blockIdx.x * 256 + threadIdx.x) * 4;
    float4 v = *(const float4*)(x + i);
    float f[4] = {v.x, v.y, v.z, v.w};
    unsigned short hs[4], ls[4];
#pragma unroll
    for (int j = 0; j < 4; j++) {
        __nv_bfloat16 h = __float2bfloat16(f[j]);
        __nv_bfloat16 l = __float2bfloat16(f[j] - __bfloat162float(h));
        hs[j] = __bfloat16_as_ushort(h);
        ls[j] = __bfloat16_as_ushort(l);
    }
    uint2 H = make_uint2(hs[0] | ((unsigned)hs[1] << 16),
                         hs[2] | ((unsigned)hs[3] << 16));
    uint2 L = make_uint2(ls[0] | ((unsigned)ls[1] << 16),
                         ls[2] | ((unsigned)ls[3] << 16));
    *(uint2*)(hi + i) = H;
    *(uint2*)(lo + i) = L;
}

// ---------------------------------------------------------------------------
// Transpose + decompose weights: Wt[n][k] = W[k][n], 4 matrices (z-dim)
// ---------------------------------------------------------------------------
__global__ void __launch_bounds__(256)
decompose_w(const float* __restrict__ w0, const float* __restrict__ w1,
            const float* __restrict__ w2, const float* __restrict__ w3,
            __nv_bfloat16* __restrict__ hi, __nv_bfloat16* __restrict__ lo)
{
    __shared__ float t[32][33];
    const int z = blockIdx.z;
    const float* W = (z == 0) ? w0 : ((z == 1) ? w1 : ((z == 2) ? w2 : w3));
    const int n0 = blockIdx.x * 32, k0 = blockIdx.y * 32;
    const int tx = threadIdx.x & 31, ty = threadIdx.x >> 5;   // 32 x 8
#pragma unroll
    for (int r = 0; r < 4; r++)
        t[ty + r * 8][tx] = W[(size_t)(k0 + ty + r * 8) * HID + n0 + tx];
    __syncthreads();
    const size_t base = (size_t)z * HID * HID;
#pragma unroll
    for (int r = 0; r < 4; r++) {
        int n = n0 + ty + r * 8;
        int k = k0 + tx;
        float v = t[tx][ty + r * 8];
        __nv_bfloat16 h = __float2bfloat16(v);
        __nv_bfloat16 l = __float2bfloat16(v - __bfloat162float(h));
        hi[base + (size_t)n * HID + k] = h;
        lo[base + (size_t)n * HID + k] = l;
    }
}

// ---------------------------------------------------------------------------
// Neighborhood attention: one warp per (b, head, s). HDIM=64 -> 2 dims/lane.
// Writes the attention output directly as bf16 hi/lo (fused decompose).
// ---------------------------------------------------------------------------
__global__ void __launch_bounds__(256)
neigh_attn_kernel(const float* __restrict__ Q, const float* __restrict__ K,
                  const float* __restrict__ V,
                  __nv_bfloat16* __restrict__ Ohi,
                  __nv_bfloat16* __restrict__ Olo)
{
    int w    = (blockIdx.x * blockDim.x + threadIdx.x) >> 5;
    int lane = threadIdx.x & 31;
    int s = w & (SEQ - 1);
    int h = (w >> 13) & (NHEADS - 1);
    int b = w >> 17;

    size_t base = ((size_t)(b * SEQ + s)) * HID + h * HDIM;
    float2 qv = *(const float2*)(Q + base + lane * 2);

    float sc[KWIN];
#pragma unroll
    for (int j = 0; j < KWIN; j++) {
        int t = s + j - KWIN / 2;
        bool valid = (t >= 0) && (t < SEQ);
        float p = 0.0f;
        if (valid) {
            size_t kb = ((size_t)(b * SEQ + t)) * HID + h * HDIM;
            float2 kv = *(const float2*)(K + kb + lane * 2);
            p = qv.x * kv.x + qv.y * kv.y;
        }
#pragma unroll
        for (int o = 16; o > 0; o >>= 1)
            p += __shfl_xor_sync(0xffffffffu, p, o);
        sc[j] = valid ? p * ATT_SCALE : -INFINITY;
    }

    float mx = sc[0];
#pragma unroll
    for (int j = 1; j < KWIN; j++) mx = fmaxf(mx, sc[j]);
    float e[KWIN], den = 0.0f;
#pragma unroll
    for (int j = 0; j < KWIN; j++) { e[j] = expf(sc[j] - mx); den += e[j]; }
    float inv = 1.0f / den;

    float2 o2 = make_float2(0.0f, 0.0f);
#pragma unroll
    for (int j = 0; j < KWIN; j++) {
        int t = s + j - KWIN / 2;
        if (t >= 0 && t < SEQ) {
            size_t vb = ((size_t)(b * SEQ + t)) * HID + h * HDIM;
            float2 vv = *(const float2*)(V + vb + lane * 2);
            float wgt = e[j] * inv;
            o2.x += wgt * vv.x;
            o2.y += wgt * vv.y;
        }
    }

    __nv_bfloat16 h0 = __float2bfloat16(o2.x);
    __nv_bfloat16 h1 = __float2bfloat16(o2.y);
    __nv_bfloat16 l0 = __float2bfloat16(o2.x - __bfloat162float(h0));
    __nv_bfloat16 l1 = __float2bfloat16(o2.y - __bfloat162float(h1));
    unsigned hiw = __bfloat16_as_ushort(h0) |
                   ((unsigned)__bfloat16_as_ushort(h1) << 16);
    unsigned low = __bfloat16_as_ushort(l0) |
                   ((unsigned)__bfloat16_as_ushort(l1) << 16);
    *(unsigned*)(Ohi + base + lane * 2) = hiw;
    *(unsigned*)(Olo + base + lane * 2) = low;
}

// ---------------------------------------------------------------------------
// Launch
// ---------------------------------------------------------------------------
extern "C" void kernel_launch(void* const* d_in, const int* in_sizes, int n_in,
                              void* d_out, int out_size)
{
    const float* hs  = (const float*)d_in[0];
    const float* w_q = (const float*)d_in[1];
    const float* b_q = (const float*)d_in[2];
    const float* w_k = (const float*)d_in[3];
    const float* b_k = (const float*)d_in[4];
    const float* w_v = (const float*)d_in[5];
    const float* b_v = (const float*)d_in[6];
    const float* w_o = (const float*)d_in[7];
    const float* b_o = (const float*)d_in[8];
    float* out = (float*)d_out;

    float *qb, *kb, *vb;
    __nv_bfloat16 *ah, *al, *oh, *ol, *wh, *wl;
    cudaGetSymbolAddress((void**)&qb, g_q);
    cudaGetSymbolAddress((void**)&kb, g_k);
    cudaGetSymbolAddress((void**)&vb, g_v);
    cudaGetSymbolAddress((void**)&ah, g_a_hi);
    cudaGetSymbolAddress((void**)&al, g_a_lo);
    cudaGetSymbolAddress((void**)&oh, g_o_hi);
    cudaGetSymbolAddress((void**)&ol, g_o_lo);
    cudaGetSymbolAddress((void**)&wh, g_w_hi);
    cudaGetSymbolAddress((void**)&wl, g_w_lo);

    cudaFuncSetAttribute(gemm_mma, cudaFuncAttributeMaxDynamicSharedMemorySize,
                         SMEMB);

    const int act_blocks = (M_ROWS * HID) / (256 * 4);   // 16384

    // 1) decompose activations + weights
    decompose_act<<<act_blocks, 256>>>(hs, ah, al);
    decompose_w<<<dim3(32, 32, 4), 256>>>(w_q, w_k, w_v, w_o, wh, wl);

    // 2) fused QKV GEMM: 3 matrices x 4 N-tiles(256) x 128 M-tiles
    gemm_mma<<<dim3(12, 128), 512, SMEMB>>>(
        ah, al, wh, wl, 0, b_q, b_k, b_v, qb, kb, vb);

    // 3) neighborhood attention (emits bf16 hi/lo directly)
    neigh_attn_kernel<<<(BATCH * NHEADS * SEQ) / 8, 256>>>(qb, kb, vb, oh, ol);

    // 4) O projection
    gemm_mma<<<dim3(4, 128), 512, SMEMB>>>(
        oh, ol, wh, wl, 3, b_o, b_o, b_o, out, out, out);
}

// round 9
// speedup vs baseline: 1.3167x; 1.3167x over previous
#include <cuda_runtime.h>
#include <cuda_fp16.h>
#include <math.h>
#include <stdint.h>

// ---------------------------------------------------------------------------
// Problem constants
// ---------------------------------------------------------------------------
#define BATCH     2
#define SEQ       8192
#define HID       1024
#define NHEADS    16
#define HDIM      64
#define KWIN      7
#define ATT_SCALE 0.125f
#define M_ROWS    (BATCH * SEQ)     // 16384

// ---------------------------------------------------------------------------
// Scratch (__device__ globals: allowed, no runtime allocation)
// ---------------------------------------------------------------------------
__device__ float g_q[(size_t)M_ROWS * HID];
__device__ float g_k[(size_t)M_ROWS * HID];
__device__ float g_v[(size_t)M_ROWS * HID];
__device__ __half g_a[(size_t)M_ROWS * HID];            // fp16 A operand (reused)
__device__ __half g_w_hi[(size_t)4 * HID * HID];        // transposed [n][k]
__device__ __half g_w_lo[(size_t)4 * HID * HID];

// ---------------------------------------------------------------------------
// PTX helpers (base sm_103 target — NO 'a'-gated features)
// ---------------------------------------------------------------------------
__device__ __forceinline__ uint32_t smem_u32(const void* p) {
    uint32_t a;
    asm("{ .reg .u64 t; cvta.to.shared.u64 t, %1; cvt.u32.u64 %0, t; }"
        : "=r"(a) : "l"(p));
    return a;
}
__device__ __forceinline__ void cp16(uint32_t s, const void* g) {
    asm volatile("cp.async.cg.shared.global [%0], [%1], 16;"
                 :: "r"(s), "l"(g));
}
__device__ __forceinline__ void ldsm_x4(uint32_t* r, uint32_t addr) {
    asm volatile("ldmatrix.sync.aligned.m8n8.x4.shared.b16 {%0,%1,%2,%3}, [%4];"
                 : "=r"(r[0]), "=r"(r[1]), "=r"(r[2]), "=r"(r[3]) : "r"(addr));
}
__device__ __forceinline__ void mma16816(float* d, const uint32_t* a,
                                         const uint32_t* b) {
    asm volatile(
        "mma.sync.aligned.m16n8k16.row.col.f32.f16.f16.f32 "
        "{%0,%1,%2,%3}, {%4,%5,%6,%7}, {%8,%9}, {%0,%1,%2,%3};"
        : "+f"(d[0]), "+f"(d[1]), "+f"(d[2]), "+f"(d[3])
        : "r"(a[0]), "r"(a[1]), "r"(a[2]), "r"(a[3]), "r"(b[0]), "r"(b[1]));
}

// ---------------------------------------------------------------------------
// GEMM config: 128x256 CTA tile, BK=32, 3-stage cp.async ring, 512 threads
// A: single fp16 tile; B: fp16 hi + lo tiles (weights pre-split)
// ---------------------------------------------------------------------------
#define PITCH   80                      // bytes per 32-elem fp16 row (64+16 pad)
#define TILE_A  (128 * PITCH)           // 10240
#define TILE_B  (256 * PITCH)           // 20480
#define OFF_BH  TILE_A                  // 10240
#define OFF_BL  (TILE_A + TILE_B)       // 30720
#define BUFB    (TILE_A + 2 * TILE_B)   // 51200 per stage
#define NSTAGE  3
#define SMEMB   (NSTAGE * BUFB)         // 153600

__device__ __forceinline__ void load_chunk(
    uint32_t base, int tid, int k0, int m0, int n0,
    const __half* __restrict__ A,
    const __half* __restrict__ Bh, const __half* __restrict__ Bl)
{
    {   // A: 128 rows x 64B — 512 cp16, 1 per thread
        int row = tid >> 2, c = tid & 3;
        uint32_t so = (uint32_t)(row * PITCH + c * 16);
        size_t go = (size_t)(m0 + row) * HID + k0 + c * 8;
        cp16(base + so, A + go);
    }
#pragma unroll
    for (int r = 0; r < 2; r++) {   // B hi/lo: 256 rows x 64B each
        int idx = tid + r * 512;
        int row = idx >> 2, c = idx & 3;
        uint32_t so = (uint32_t)(row * PITCH + c * 16);
        size_t go = (size_t)(n0 + row) * HID + k0 + c * 8;
        cp16(base + OFF_BH + so, Bh + go);
        cp16(base + OFF_BL + so, Bl + go);
    }
    asm volatile("cp.async.commit_group;" ::: "memory");
}

// C[m][n] = sum_k A[m][k]*(Wh+Wl)t[n][k] + bias[n], 2-pass fp16 split HMMA.
// grid.x: (matrix_within_launch << 2) | n_tile;  grid.y: m_tile
__global__ void __launch_bounds__(512, 1)
gemm_mma(const __half* __restrict__ A,
         const __half* __restrict__ Wh, const __half* __restrict__ Wl,
         int mat_base,
         const float* __restrict__ bias0, const float* __restrict__ bias1,
         const float* __restrict__ bias2,
         float* __restrict__ c0, float* __restrict__ c1, float* __restrict__ c2)
{
    extern __shared__ char smem[];
    const uint32_t sb = smem_u32(smem);
    const int tid  = threadIdx.x;
    const int lane = tid & 31;
    const int wid  = tid >> 5;          // 0..15
    const int wm   = wid >> 3;          // 0..1 -> 64-row slab
    const int wn   = wid & 7;           // 0..7 -> 32-col slab
    const int mi_  = blockIdx.x >> 2;   // matrix within launch
    const int n0   = (blockIdx.x & 3) * 256;
    const int m0   = blockIdx.y * 128;

    const __half* Bh = Wh + (size_t)(mat_base + mi_) * HID * HID;
    const __half* Bl = Wl + (size_t)(mat_base + mi_) * HID * HID;
    const float* bias = (mi_ == 0) ? bias0 : ((mi_ == 1) ? bias1 : bias2);
    float* C = (mi_ == 0) ? c0 : ((mi_ == 1) ? c1 : c2);

    float acc[4][4][4];
#pragma unroll
    for (int i = 0; i < 4; i++)
#pragma unroll
        for (int j = 0; j < 4; j++)
#pragma unroll
            for (int r = 0; r < 4; r++) acc[i][j][r] = 0.0f;

    // prologue: stages 0,1
    load_chunk(sb,        tid, 0,  m0, n0, A, Bh, Bl);
    load_chunk(sb + BUFB, tid, 32, m0, n0, A, Bh, Bl);

    // per-thread ldmatrix source offsets (verified R6/R7 layout)
    const int mrow = lane >> 3;
    const int jrow = lane & 7;
    const uint32_t a_off = (uint32_t)((wm * 64 + (mrow & 1) * 8 + jrow) * PITCH
                                      + (mrow >> 1) * 16);
    const uint32_t b_off = (uint32_t)((wn * 32 + (mrow >> 1) * 8 + jrow) * PITCH
                                      + (mrow & 1) * 16) + OFF_BH;

    const int NCHUNK = HID / 32;        // 32
    uint32_t stage_base[NSTAGE] = {sb, sb + BUFB, sb + 2 * BUFB};
    int st = 0;

    for (int ck = 0; ck < NCHUNK; ck++) {
        if (ck < NCHUNK - 2) asm volatile("cp.async.wait_group 1;" ::: "memory");
        else                 asm volatile("cp.async.wait_group 0;" ::: "memory");
        __syncthreads();   // chunk ck visible; all warps done with chunk ck-1

        if (ck + 2 < NCHUNK) {
            int ls = st + 2; if (ls >= NSTAGE) ls -= NSTAGE;
            load_chunk(stage_base[ls], tid, (ck + 2) * 32, m0, n0, A, Bh, Bl);
        }

        const uint32_t base = stage_base[st];
#pragma unroll
        for (int ks = 0; ks < 2; ks++) {
            const uint32_t kb = ks * 32;
            uint32_t bh[2][4], bl[2][4];
#pragma unroll
            for (int nj = 0; nj < 2; nj++) {
                uint32_t bd = base + b_off + nj * 16 * PITCH + kb;
                ldsm_x4(bh[nj], bd);
                ldsm_x4(bl[nj], bd + TILE_B);   // OFF_BL - OFF_BH
            }
#pragma unroll
            for (int mi = 0; mi < 4; mi++) {
                uint32_t ah[4];
                ldsm_x4(ah, base + a_off + mi * 16 * PITCH + kb);
#pragma unroll
                for (int ni = 0; ni < 4; ni++) {
                    const uint32_t* ph = &bh[ni >> 1][(ni & 1) * 2];
                    const uint32_t* pl = &bl[ni >> 1][(ni & 1) * 2];
                    mma16816(acc[mi][ni], ah, ph);   // A*Wh
                    mma16816(acc[mi][ni], ah, pl);   // A*Wl
                }
            }
        }
        if (++st == NSTAGE) st = 0;
    }

    // epilogue: fragment layout -> C, add bias
    const int grp = lane >> 2, t4 = lane & 3;
#pragma unroll
    for (int ni = 0; ni < 4; ni++) {
        const int col = n0 + wn * 32 + ni * 8 + t4 * 2;
        const float bv0 = bias[col], bv1 = bias[col + 1];
#pragma unroll
        for (int mi = 0; mi < 4; mi++) {
            const int r0 = m0 + wm * 64 + mi * 16 + grp;
            *(float2*)(C + (size_t)r0 * HID + col) =
                make_float2(acc[mi][ni][0] + bv0, acc[mi][ni][1] + bv1);
            *(float2*)(C + (size_t)(r0 + 8) * HID + col) =
                make_float2(acc[mi][ni][2] + bv0, acc[mi][ni][3] + bv1);
        }
    }
}

// ---------------------------------------------------------------------------
// Convert fp32 -> fp16 (elementwise, for activations)
// ---------------------------------------------------------------------------
__global__ void __launch_bounds__(256)
convert_act(const float* __restrict__ x, __half* __restrict__ y)
{
    size_t i = ((size_t)blockIdx.x * 256 + threadIdx.x) * 4;
    float4 v = *(const float4*)(x + i);
    __half2 p0 = __floats2half2_rn(v.x, v.y);
    __half2 p1 = __floats2half2_rn(v.z, v.w);
    *(uint2*)(y + i) = make_uint2(*(uint32_t*)&p0, *(uint32_t*)&p1);
}

// ---------------------------------------------------------------------------
// Transpose + split weights: Wt[n][k] = W[k][n] as fp16 hi + lo, 4 matrices
// ---------------------------------------------------------------------------
__global__ void __launch_bounds__(256)
decompose_w(const float* __restrict__ w0, const float* __restrict__ w1,
            const float* __restrict__ w2, const float* __restrict__ w3,
            __half* __restrict__ hi, __half* __restrict__ lo)
{
    __shared__ float t[32][33];
    const int z = blockIdx.z;
    const float* W = (z == 0) ? w0 : ((z == 1) ? w1 : ((z == 2) ? w2 : w3));
    const int n0 = blockIdx.x * 32, k0 = blockIdx.y * 32;
    const int tx = threadIdx.x & 31, ty = threadIdx.x >> 5;   // 32 x 8
#pragma unroll
    for (int r = 0; r < 4; r++)
        t[ty + r * 8][tx] = W[(size_t)(k0 + ty + r * 8) * HID + n0 + tx];
    __syncthreads();
    const size_t base = (size_t)z * HID * HID;
#pragma unroll
    for (int r = 0; r < 4; r++) {
        int n = n0 + ty + r * 8;
        int k = k0 + tx;
        float v = t[tx][ty + r * 8];
        __half h = __float2half_rn(v);
        __half l = __float2half_rn(v - __half2float(h));
        hi[base + (size_t)n * HID + k] = h;
        lo[base + (size_t)n * HID + k] = l;
    }
}

// ---------------------------------------------------------------------------
// Neighborhood attention: one warp per (b, head, s). HDIM=64 -> 2 dims/lane.
// Writes the attention output directly as fp16 (A operand of the O-GEMM).
// ---------------------------------------------------------------------------
__global__ void __launch_bounds__(256)
neigh_attn_kernel(const float* __restrict__ Q, const float* __restrict__ K,
                  const float* __restrict__ V, __half* __restrict__ Oh)
{
    int w    = (blockIdx.x * blockDim.x + threadIdx.x) >> 5;
    int lane = threadIdx.x & 31;
    int s = w & (SEQ - 1);
    int h = (w >> 13) & (NHEADS - 1);
    int b = w >> 17;

    size_t base = ((size_t)(b * SEQ + s)) * HID + h * HDIM;
    float2 qv = *(const float2*)(Q + base + lane * 2);

    float sc[KWIN];
#pragma unroll
    for (int j = 0; j < KWIN; j++) {
        int t = s + j - KWIN / 2;
        bool valid = (t >= 0) && (t < SEQ);
        float p = 0.0f;
        if (valid) {
            size_t kb = ((size_t)(b * SEQ + t)) * HID + h * HDIM;
            float2 kv = *(const float2*)(K + kb + lane * 2);
            p = qv.x * kv.x + qv.y * kv.y;
        }
#pragma unroll
        for (int o = 16; o > 0; o >>= 1)
            p += __shfl_xor_sync(0xffffffffu, p, o);
        sc[j] = valid ? p * ATT_SCALE : -INFINITY;
    }

    float mx = sc[0];
#pragma unroll
    for (int j = 1; j < KWIN; j++) mx = fmaxf(mx, sc[j]);
    float e[KWIN], den = 0.0f;
#pragma unroll
    for (int j = 0; j < KWIN; j++) { e[j] = expf(sc[j] - mx); den += e[j]; }
    float inv = 1.0f / den;

    float2 o2 = make_float2(0.0f, 0.0f);
#pragma unroll
    for (int j = 0; j < KWIN; j++) {
        int t = s + j - KWIN / 2;
        if (t >= 0 && t < SEQ) {
            size_t vb = ((size_t)(b * SEQ + t)) * HID + h * HDIM;
            float2 vv = *(const float2*)(V + vb + lane * 2);
            float wgt = e[j] * inv;
            o2.x += wgt * vv.x;
            o2.y += wgt * vv.y;
        }
    }

    __half2 p = __floats2half2_rn(o2.x, o2.y);
    *(uint32_t*)(Oh + base + lane * 2) = *(uint32_t*)&p;
}

// ---------------------------------------------------------------------------
// Launch
// ---------------------------------------------------------------------------
extern "C" void kernel_launch(void* const* d_in, const int* in_sizes, int n_in,
                              void* d_out, int out_size)
{
    const float* hs  = (const float*)d_in[0];
    const float* w_q = (const float*)d_in[1];
    const float* b_q = (const float*)d_in[2];
    const float* w_k = (const float*)d_in[3];
    const float* b_k = (const float*)d_in[4];
    const float* w_v = (const float*)d_in[5];
    const float* b_v = (const float*)d_in[6];
    const float* w_o = (const float*)d_in[7];
    const float* b_o = (const float*)d_in[8];
    float* out = (float*)d_out;

    float *qb, *kb, *vb;
    __half *ab, *wh, *wl;
    cudaGetSymbolAddress((void**)&qb, g_q);
    cudaGetSymbolAddress((void**)&kb, g_k);
    cudaGetSymbolAddress((void**)&vb, g_v);
    cudaGetSymbolAddress((void**)&ab, g_a);
    cudaGetSymbolAddress((void**)&wh, g_w_hi);
    cudaGetSymbolAddress((void**)&wl, g_w_lo);

    cudaFuncSetAttribute(gemm_mma, cudaFuncAttributeMaxDynamicSharedMemorySize,
                         SMEMB);

    const int act_blocks = (M_ROWS * HID) / (256 * 4);   // 16384

    // 1) convert activations to fp16; split+transpose weights
    convert_act<<<act_blocks, 256>>>(hs, ab);
    decompose_w<<<dim3(32, 32, 4), 256>>>(w_q, w_k, w_v, w_o, wh, wl);

    // 2) fused QKV GEMM: 3 matrices x 4 N-tiles(256) x 128 M-tiles
    gemm_mma<<<dim3(12, 128), 512, SMEMB>>>(
        ab, wh, wl, 0, b_q, b_k, b_v, qb, kb, vb);

    // 3) neighborhood attention (writes fp16 A operand in place)
    neigh_attn_kernel<<<(BATCH * NHEADS * SEQ) / 8, 256>>>(qb, kb, vb, ab);

    // 4) O projection
    gemm_mma<<<dim3(4, 128), 512, SMEMB>>>(
        ab, wh, wl, 3, b_o, b_o, b_o, out, out, out);
}

// round 10
// speedup vs baseline: 2.1074x; 1.6006x over previous
#include <cuda_runtime.h>
#include <cuda_fp16.h>
#include <math.h>
#include <stdint.h>

// ---------------------------------------------------------------------------
// Problem constants
// ---------------------------------------------------------------------------
#define BATCH     2
#define SEQ       8192
#define HID       1024
#define NHEADS    16
#define HDIM      64
#define KWIN      7
#define ATT_SCALE 0.125f
#define M_ROWS    (BATCH * SEQ)     // 16384

// ---------------------------------------------------------------------------
// Scratch (__device__ globals: allowed, no runtime allocation)
// ---------------------------------------------------------------------------
__device__ __half g_q[(size_t)M_ROWS * HID];
__device__ __half g_k[(size_t)M_ROWS * HID];
__device__ __half g_v[(size_t)M_ROWS * HID];
__device__ __half g_a[(size_t)M_ROWS * HID];      // fp16 A operand (reused)
__device__ __half g_w[(size_t)4 * HID * HID];     // transposed [n][k], fp16

// ---------------------------------------------------------------------------
// PTX helpers (base sm_103 target — NO 'a'-gated features)
// ---------------------------------------------------------------------------
__device__ __forceinline__ uint32_t smem_u32(const void* p) {
    uint32_t a;
    asm("{ .reg .u64 t; cvta.to.shared.u64 t, %1; cvt.u32.u64 %0, t; }"
        : "=r"(a) : "l"(p));
    return a;
}
__device__ __forceinline__ void cp16(uint32_t s, const void* g) {
    asm volatile("cp.async.cg.shared.global [%0], [%1], 16;"
                 :: "r"(s), "l"(g));
}
__device__ __forceinline__ void ldsm_x4(uint32_t* r, uint32_t addr) {
    asm volatile("ldmatrix.sync.aligned.m8n8.x4.shared.b16 {%0,%1,%2,%3}, [%4];"
                 : "=r"(r[0]), "=r"(r[1]), "=r"(r[2]), "=r"(r[3]) : "r"(addr));
}
__device__ __forceinline__ void mma16816(float* d, const uint32_t* a,
                                         const uint32_t* b) {
    asm volatile(
        "mma.sync.aligned.m16n8k16.row.col.f32.f16.f16.f32 "
        "{%0,%1,%2,%3}, {%4,%5,%6,%7}, {%8,%9}, {%0,%1,%2,%3};"
        : "+f"(d[0]), "+f"(d[1]), "+f"(d[2]), "+f"(d[3])
        : "r"(a[0]), "r"(a[1]), "r"(a[2]), "r"(a[3]), "r"(b[0]), "r"(b[1]));
}

// ---------------------------------------------------------------------------
// GEMM config: 128x256 CTA tile, BK=32, 4-stage cp.async ring, 512 threads
// Single-pass fp16: A tile + one B tile per stage.
// ---------------------------------------------------------------------------
#define PITCH   80                      // bytes per 32-elem fp16 row (64+16 pad)
#define TILE_A  (128 * PITCH)           // 10240
#define TILE_B  (256 * PITCH)           // 20480
#define OFF_B   TILE_A                  // 10240
#define BUFB    (TILE_A + TILE_B)       // 30720 per stage
#define NSTAGE  4
#define SMEMB   (NSTAGE * BUFB)         // 122880

__device__ __forceinline__ void load_chunk(
    uint32_t base, int tid, int k0, int m0, int n0,
    const __half* __restrict__ A, const __half* __restrict__ B)
{
    {   // A: 128 rows x 64B — 512 cp16, 1 per thread
        int row = tid >> 2, c = tid & 3;
        uint32_t so = (uint32_t)(row * PITCH + c * 16);
        size_t go = (size_t)(m0 + row) * HID + k0 + c * 8;
        cp16(base + so, A + go);
    }
#pragma unroll
    for (int r = 0; r < 2; r++) {   // B: 256 rows x 64B — 1024 cp16
        int idx = tid + r * 512;
        int row = idx >> 2, c = idx & 3;
        uint32_t so = (uint32_t)(row * PITCH + c * 16);
        size_t go = (size_t)(n0 + row) * HID + k0 + c * 8;
        cp16(base + OFF_B + so, B + go);
    }
    asm volatile("cp.async.commit_group;" ::: "memory");
}

// C[m][n] = sum_k A[m][k]*Wt[n][k] + bias[n], single-pass fp16 HMMA.
// HALF_OUT: store fp16 (QKV path) vs fp32 (output projection).
// grid.x: (matrix_within_launch << 2) | n_tile;  grid.y: m_tile
template <bool HALF_OUT>
__global__ void __launch_bounds__(512, 1)
gemm_mma(const __half* __restrict__ A, const __half* __restrict__ W,
         int mat_base,
         const float* __restrict__ bias0, const float* __restrict__ bias1,
         const float* __restrict__ bias2,
         void* __restrict__ c0v, void* __restrict__ c1v, void* __restrict__ c2v)
{
    extern __shared__ char smem[];
    const uint32_t sb = smem_u32(smem);
    const int tid  = threadIdx.x;
    const int lane = tid & 31;
    const int wid  = tid >> 5;          // 0..15
    const int wm   = wid >> 3;          // 0..1 -> 64-row slab
    const int wn   = wid & 7;           // 0..7 -> 32-col slab
    const int mi_  = blockIdx.x >> 2;   // matrix within launch
    const int n0   = (blockIdx.x & 3) * 256;
    const int m0   = blockIdx.y * 128;

    const __half* B = W + (size_t)(mat_base + mi_) * HID * HID;
    const float* bias = (mi_ == 0) ? bias0 : ((mi_ == 1) ? bias1 : bias2);
    void* Cv = (mi_ == 0) ? c0v : ((mi_ == 1) ? c1v : c2v);

    float acc[4][4][4];
#pragma unroll
    for (int i = 0; i < 4; i++)
#pragma unroll
        for (int j = 0; j < 4; j++)
#pragma unroll
            for (int r = 0; r < 4; r++) acc[i][j][r] = 0.0f;

    // prologue: stages 0,1,2
    load_chunk(sb,            tid, 0,  m0, n0, A, B);
    load_chunk(sb + BUFB,     tid, 32, m0, n0, A, B);
    load_chunk(sb + 2 * BUFB, tid, 64, m0, n0, A, B);

    // per-thread ldmatrix source offsets (verified R6-R9 layout)
    const int mrow = lane >> 3;
    const int jrow = lane & 7;
    const uint32_t a_off = (uint32_t)((wm * 64 + (mrow & 1) * 8 + jrow) * PITCH
                                      + (mrow >> 1) * 16);
    const uint32_t b_off = (uint32_t)((wn * 32 + (mrow >> 1) * 8 + jrow) * PITCH
                                      + (mrow & 1) * 16) + OFF_B;

    const int NCHUNK = HID / 32;        // 32
    int st = 0;                         // stage of current chunk

    for (int ck = 0; ck < NCHUNK; ck++) {
        if (ck <= NCHUNK - 3)      asm volatile("cp.async.wait_group 2;" ::: "memory");
        else if (ck == NCHUNK - 2) asm volatile("cp.async.wait_group 1;" ::: "memory");
        else                       asm volatile("cp.async.wait_group 0;" ::: "memory");
        __syncthreads();   // chunk ck visible; all warps done with chunk ck-1

        // prefetch chunk ck+3 into the stage freed at iter ck-1
        if (ck + 3 < NCHUNK) {
            int ls = st + 3; if (ls >= NSTAGE) ls -= NSTAGE;
            load_chunk(sb + ls * BUFB, tid, (ck + 3) * 32, m0, n0, A, B);
        }

        const uint32_t base = sb + st * BUFB;
#pragma unroll
        for (int ks = 0; ks < 2; ks++) {
            const uint32_t kb = ks * 32;
            uint32_t bf[2][4];
#pragma unroll
            for (int nj = 0; nj < 2; nj++)
                ldsm_x4(bf[nj], base + b_off + nj * 16 * PITCH + kb);
#pragma unroll
            for (int mi = 0; mi < 4; mi++) {
                uint32_t ah[4];
                ldsm_x4(ah, base + a_off + mi * 16 * PITCH + kb);
#pragma unroll
                for (int ni = 0; ni < 4; ni++)
                    mma16816(acc[mi][ni], ah, &bf[ni >> 1][(ni & 1) * 2]);
            }
        }
        if (++st == NSTAGE) st = 0;
    }

    // epilogue: fragment layout -> C, add bias
    const int grp = lane >> 2, t4 = lane & 3;
#pragma unroll
    for (int ni = 0; ni < 4; ni++) {
        const int col = n0 + wn * 32 + ni * 8 + t4 * 2;
        const float bv0 = bias[col], bv1 = bias[col + 1];
#pragma unroll
        for (int mi = 0; mi < 4; mi++) {
            const int r0 = m0 + wm * 64 + mi * 16 + grp;
            if (HALF_OUT) {
                __half* C = (__half*)Cv;
                __half2 p0 = __floats2half2_rn(acc[mi][ni][0] + bv0,
                                               acc[mi][ni][1] + bv1);
                __half2 p1 = __floats2half2_rn(acc[mi][ni][2] + bv0,
                                               acc[mi][ni][3] + bv1);
                *(uint32_t*)(C + (size_t)r0 * HID + col)       = *(uint32_t*)&p0;
                *(uint32_t*)(C + (size_t)(r0 + 8) * HID + col) = *(uint32_t*)&p1;
            } else {
                float* C = (float*)Cv;
                *(float2*)(C + (size_t)r0 * HID + col) =
                    make_float2(acc[mi][ni][0] + bv0, acc[mi][ni][1] + bv1);
                *(float2*)(C + (size_t)(r0 + 8) * HID + col) =
                    make_float2(acc[mi][ni][2] + bv0, acc[mi][ni][3] + bv1);
            }
        }
    }
}

// ---------------------------------------------------------------------------
// Convert fp32 -> fp16 (elementwise, for activations)
// ---------------------------------------------------------------------------
__global__ void __launch_bounds__(256)
convert_act(const float* __restrict__ x, __half* __restrict__ y)
{
    size_t i = ((size_t)blockIdx.x * 256 + threadIdx.x) * 4;
    float4 v = *(const float4*)(x + i);
    __half2 p0 = __floats2half2_rn(v.x, v.y);
    __half2 p1 = __floats2half2_rn(v.z, v.w);
    *(uint2*)(y + i) = make_uint2(*(uint32_t*)&p0, *(uint32_t*)&p1);
}

// ---------------------------------------------------------------------------
// Transpose + round weights: Wt[n][k] = fp16(W[k][n]), 4 matrices (z-dim)
// ---------------------------------------------------------------------------
__global__ void __launch_bounds__(256)
transpose_w(const float* __restrict__ w0, const float* __restrict__ w1,
            const float* __restrict__ w2, const float* __restrict__ w3,
            __half* __restrict__ wt)
{
    __shared__ float t[32][33];
    const int z = blockIdx.z;
    const float* W = (z == 0) ? w0 : ((z == 1) ? w1 : ((z == 2) ? w2 : w3));
    const int n0 = blockIdx.x * 32, k0 = blockIdx.y * 32;
    const int tx = threadIdx.x & 31, ty = threadIdx.x >> 5;   // 32 x 8
#pragma unroll
    for (int r = 0; r < 4; r++)
        t[ty + r * 8][tx] = W[(size_t)(k0 + ty + r * 8) * HID + n0 + tx];
    __syncthreads();
    const size_t base = (size_t)z * HID * HID;
#pragma unroll
    for (int r = 0; r < 4; r++) {
        int n = n0 + ty + r * 8;
        int k = k0 + tx;
        wt[base + (size_t)n * HID + k] = __float2half_rn(t[tx][ty + r * 8]);
    }
}

// ---------------------------------------------------------------------------
// Neighborhood attention: one warp per (b, head, s). HDIM=64 -> 2 dims/lane.
// fp16 Q/K/V in, fp32 math, fp16 out (A operand of the O-GEMM).
// ---------------------------------------------------------------------------
__global__ void __launch_bounds__(256)
neigh_attn_kernel(const __half* __restrict__ Q, const __half* __restrict__ K,
                  const __half* __restrict__ V, __half* __restrict__ Oh)
{
    int w    = (blockIdx.x * blockDim.x + threadIdx.x) >> 5;
    int lane = threadIdx.x & 31;
    int s = w & (SEQ - 1);
    int h = (w >> 13) & (NHEADS - 1);
    int b = w >> 17;

    size_t base = ((size_t)(b * SEQ + s)) * HID + h * HDIM;
    float2 qv = __half22float2(*(const __half2*)(Q + base + lane * 2));

    float sc[KWIN];
#pragma unroll
    for (int j = 0; j < KWIN; j++) {
        int t = s + j - KWIN / 2;
        bool valid = (t >= 0) && (t < SEQ);
        float p = 0.0f;
        if (valid) {
            size_t kb = ((size_t)(b * SEQ + t)) * HID + h * HDIM;
            float2 kv = __half22float2(*(const __half2*)(K + kb + lane * 2));
            p = qv.x * kv.x + qv.y * kv.y;
        }
#pragma unroll
        for (int o = 16; o > 0; o >>= 1)
            p += __shfl_xor_sync(0xffffffffu, p, o);
        sc[j] = valid ? p * ATT_SCALE : -INFINITY;
    }

    float mx = sc[0];
#pragma unroll
    for (int j = 1; j < KWIN; j++) mx = fmaxf(mx, sc[j]);
    float e[KWIN], den = 0.0f;
#pragma unroll
    for (int j = 0; j < KWIN; j++) { e[j] = expf(sc[j] - mx); den += e[j]; }
    float inv = 1.0f / den;

    float2 o2 = make_float2(0.0f, 0.0f);
#pragma unroll
    for (int j = 0; j < KWIN; j++) {
        int t = s + j - KWIN / 2;
        if (t >= 0 && t < SEQ) {
            size_t vb = ((size_t)(b * SEQ + t)) * HID + h * HDIM;
            float2 vv = __half22float2(*(const __half2*)(V + vb + lane * 2));
            float wgt = e[j] * inv;
            o2.x += wgt * vv.x;
            o2.y += wgt * vv.y;
        }
    }

    __half2 p = __floats2half2_rn(o2.x, o2.y);
    *(uint32_t*)(Oh + base + lane * 2) = *(uint32_t*)&p;
}

// ---------------------------------------------------------------------------
// Launch
// ---------------------------------------------------------------------------
extern "C" void kernel_launch(void* const* d_in, const int* in_sizes, int n_in,
                              void* d_out, int out_size)
{
    const float* hs  = (const float*)d_in[0];
    const float* w_q = (const float*)d_in[1];
    const float* b_q = (const float*)d_in[2];
    const float* w_k = (const float*)d_in[3];
    const float* b_k = (const float*)d_in[4];
    const float* w_v = (const float*)d_in[5];
    const float* b_v = (const float*)d_in[6];
    const float* w_o = (const float*)d_in[7];
    const float* b_o = (const float*)d_in[8];
    float* out = (float*)d_out;

    __half *qb, *kb, *vb, *ab, *wt;
    cudaGetSymbolAddress((void**)&qb, g_q);
    cudaGetSymbolAddress((void**)&kb, g_k);
    cudaGetSymbolAddress((void**)&vb, g_v);
    cudaGetSymbolAddress((void**)&ab, g_a);
    cudaGetSymbolAddress((void**)&wt, g_w);

    cudaFuncSetAttribute(gemm_mma<true>,
                         cudaFuncAttributeMaxDynamicSharedMemorySize, SMEMB);
    cudaFuncSetAttribute(gemm_mma<false>,
                         cudaFuncAttributeMaxDynamicSharedMemorySize, SMEMB);

    const int act_blocks = (M_ROWS * HID) / (256 * 4);   // 16384

    // 1) convert activations to fp16; transpose+round weights
    convert_act<<<act_blocks, 256>>>(hs, ab);
    transpose_w<<<dim3(32, 32, 4), 256>>>(w_q, w_k, w_v, w_o, wt);

    // 2) fused QKV GEMM: 3 matrices x 4 N-tiles(256) x 128 M-tiles -> fp16
    gemm_mma<true><<<dim3(12, 128), 512, SMEMB>>>(
        ab, wt, 0, b_q, b_k, b_v, qb, kb, vb);

    // 3) neighborhood attention (fp16 in, fp16 out into A operand)
    neigh_attn_kernel<<<(BATCH * NHEADS * SEQ) / 8, 256>>>(qb, kb, vb, ab);

    // 4) O projection -> fp32 output
    gemm_mma<false><<<dim3(4, 128), 512, SMEMB>>>(
        ab, wt, 3, b_o, b_o, b_o, out, out, out);
}

// round 11
// speedup vs baseline: 2.3707x; 1.1249x over previous
#include <cuda_runtime.h>
#include <cuda_fp16.h>
#include <math.h>
#include <stdint.h>

// ---------------------------------------------------------------------------
// Problem constants
// ---------------------------------------------------------------------------
#define BATCH     2
#define SEQ       8192
#define HID       1024
#define NHEADS    16
#define HDIM      64
#define KWIN      7
#define ATT_SCALE 0.125f
#define M_ROWS    (BATCH * SEQ)     // 16384

// ---------------------------------------------------------------------------
// Scratch (__device__ globals: allowed, no runtime allocation)
// ---------------------------------------------------------------------------
__device__ __half g_q[(size_t)M_ROWS * HID];
__device__ __half g_k[(size_t)M_ROWS * HID];
__device__ __half g_v[(size_t)M_ROWS * HID];
__device__ __half g_a[(size_t)M_ROWS * HID];      // fp16 A operand (reused)
__device__ __half g_w[(size_t)4 * HID * HID];     // transposed [n][k], fp16

// ---------------------------------------------------------------------------
// PTX helpers (base sm_103 target — NO 'a'-gated features)
// ---------------------------------------------------------------------------
__device__ __forceinline__ uint32_t smem_u32(const void* p) {
    uint32_t a;
    asm("{ .reg .u64 t; cvta.to.shared.u64 t, %1; cvt.u32.u64 %0, t; }"
        : "=r"(a) : "l"(p));
    return a;
}
__device__ __forceinline__ void cp16(uint32_t s, const void* g) {
    asm volatile("cp.async.cg.shared.global [%0], [%1], 16;"
                 :: "r"(s), "l"(g));
}
__device__ __forceinline__ void ldsm_x4(uint32_t* r, uint32_t addr) {
    asm volatile("ldmatrix.sync.aligned.m8n8.x4.shared.b16 {%0,%1,%2,%3}, [%4];"
                 : "=r"(r[0]), "=r"(r[1]), "=r"(r[2]), "=r"(r[3]) : "r"(addr));
}
__device__ __forceinline__ void ldsm_x4_t(uint32_t* r, uint32_t addr) {
    asm volatile("ldmatrix.sync.aligned.m8n8.x4.trans.shared.b16 {%0,%1,%2,%3}, [%4];"
                 : "=r"(r[0]), "=r"(r[1]), "=r"(r[2]), "=r"(r[3]) : "r"(addr));
}
__device__ __forceinline__ void mma16816(float* d, const uint32_t* a,
                                         const uint32_t* b) {
    asm volatile(
        "mma.sync.aligned.m16n8k16.row.col.f32.f16.f16.f32 "
        "{%0,%1,%2,%3}, {%4,%5,%6,%7}, {%8,%9}, {%0,%1,%2,%3};"
        : "+f"(d[0]), "+f"(d[1]), "+f"(d[2]), "+f"(d[3])
        : "r"(a[0]), "r"(a[1]), "r"(a[2]), "r"(a[3]), "r"(b[0]), "r"(b[1]));
}

// ---------------------------------------------------------------------------
// GEMM config: 128x256 CTA tile, BK=32, 4-stage cp.async ring, 512 threads
// (unchanged from R10 — verified)
// ---------------------------------------------------------------------------
#define PITCH   80
#define TILE_A  (128 * PITCH)
#define TILE_B  (256 * PITCH)
#define OFF_B   TILE_A
#define BUFB    (TILE_A + TILE_B)
#define NSTAGE  4
#define SMEMB   (NSTAGE * BUFB)         // 122880

__device__ __forceinline__ void load_chunk(
    uint32_t base, int tid, int k0, int m0, int n0,
    const __half* __restrict__ A, const __half* __restrict__ B)
{
    {
        int row = tid >> 2, c = tid & 3;
        uint32_t so = (uint32_t)(row * PITCH + c * 16);
        size_t go = (size_t)(m0 + row) * HID + k0 + c * 8;
        cp16(base + so, A + go);
    }
#pragma unroll
    for (int r = 0; r < 2; r++) {
        int idx = tid + r * 512;
        int row = idx >> 2, c = idx & 3;
        uint32_t so = (uint32_t)(row * PITCH + c * 16);
        size_t go = (size_t)(n0 + row) * HID + k0 + c * 8;
        cp16(base + OFF_B + so, B + go);
    }
    asm volatile("cp.async.commit_group;" ::: "memory");
}

template <bool HALF_OUT>
__global__ void __launch_bounds__(512, 1)
gemm_mma(const __half* __restrict__ A, const __half* __restrict__ W,
         int mat_base,
         const float* __restrict__ bias0, const float* __restrict__ bias1,
         const float* __restrict__ bias2,
         void* __restrict__ c0v, void* __restrict__ c1v, void* __restrict__ c2v)
{
    extern __shared__ char smem[];
    const uint32_t sb = smem_u32(smem);
    const int tid  = threadIdx.x;
    const int lane = tid & 31;
    const int wid  = tid >> 5;
    const int wm   = wid >> 3;
    const int wn   = wid & 7;
    const int mi_  = blockIdx.x >> 2;
    const int n0   = (blockIdx.x & 3) * 256;
    const int m0   = blockIdx.y * 128;

    const __half* B = W + (size_t)(mat_base + mi_) * HID * HID;
    const float* bias = (mi_ == 0) ? bias0 : ((mi_ == 1) ? bias1 : bias2);
    void* Cv = (mi_ == 0) ? c0v : ((mi_ == 1) ? c1v : c2v);

    float acc[4][4][4];
#pragma unroll
    for (int i = 0; i < 4; i++)
#pragma unroll
        for (int j = 0; j < 4; j++)
#pragma unroll
            for (int r = 0; r < 4; r++) acc[i][j][r] = 0.0f;

    load_chunk(sb,            tid, 0,  m0, n0, A, B);
    load_chunk(sb + BUFB,     tid, 32, m0, n0, A, B);
    load_chunk(sb + 2 * BUFB, tid, 64, m0, n0, A, B);

    const int mrow = lane >> 3;
    const int jrow = lane & 7;
    const uint32_t a_off = (uint32_t)((wm * 64 + (mrow & 1) * 8 + jrow) * PITCH
                                      + (mrow >> 1) * 16);
    const uint32_t b_off = (uint32_t)((wn * 32 + (mrow >> 1) * 8 + jrow) * PITCH
                                      + (mrow & 1) * 16) + OFF_B;

    const int NCHUNK = HID / 32;
    int st = 0;

    for (int ck = 0; ck < NCHUNK; ck++) {
        if (ck <= NCHUNK - 3)      asm volatile("cp.async.wait_group 2;" ::: "memory");
        else if (ck == NCHUNK - 2) asm volatile("cp.async.wait_group 1;" ::: "memory");
        else                       asm volatile("cp.async.wait_group 0;" ::: "memory");
        __syncthreads();

        if (ck + 3 < NCHUNK) {
            int ls = st + 3; if (ls >= NSTAGE) ls -= NSTAGE;
            load_chunk(sb + ls * BUFB, tid, (ck + 3) * 32, m0, n0, A, B);
        }

        const uint32_t base = sb + st * BUFB;
#pragma unroll
        for (int ks = 0; ks < 2; ks++) {
            const uint32_t kb = ks * 32;
            uint32_t bf[2][4];
#pragma unroll
            for (int nj = 0; nj < 2; nj++)
                ldsm_x4(bf[nj], base + b_off + nj * 16 * PITCH + kb);
#pragma unroll
            for (int mi = 0; mi < 4; mi++) {
                uint32_t ah[4];
                ldsm_x4(ah, base + a_off + mi * 16 * PITCH + kb);
#pragma unroll
                for (int ni = 0; ni < 4; ni++)
                    mma16816(acc[mi][ni], ah, &bf[ni >> 1][(ni & 1) * 2]);
            }
        }
        if (++st == NSTAGE) st = 0;
    }

    const int grp = lane >> 2, t4 = lane & 3;
#pragma unroll
    for (int ni = 0; ni < 4; ni++) {
        const int col = n0 + wn * 32 + ni * 8 + t4 * 2;
        const float bv0 = bias[col], bv1 = bias[col + 1];
#pragma unroll
        for (int mi = 0; mi < 4; mi++) {
            const int r0 = m0 + wm * 64 + mi * 16 + grp;
            if (HALF_OUT) {
                __half* C = (__half*)Cv;
                __half2 p0 = __floats2half2_rn(acc[mi][ni][0] + bv0,
                                               acc[mi][ni][1] + bv1);
                __half2 p1 = __floats2half2_rn(acc[mi][ni][2] + bv0,
                                               acc[mi][ni][3] + bv1);
                *(uint32_t*)(C + (size_t)r0 * HID + col)       = *(uint32_t*)&p0;
                *(uint32_t*)(C + (size_t)(r0 + 8) * HID + col) = *(uint32_t*)&p1;
            } else {
                float* C = (float*)Cv;
                *(float2*)(C + (size_t)r0 * HID + col) =
                    make_float2(acc[mi][ni][0] + bv0, acc[mi][ni][1] + bv1);
                *(float2*)(C + (size_t)(r0 + 8) * HID + col) =
                    make_float2(acc[mi][ni][2] + bv0, acc[mi][ni][3] + bv1);
            }
        }
    }
}

// ---------------------------------------------------------------------------
// Convert fp32 -> fp16 (elementwise, for activations)
// ---------------------------------------------------------------------------
__global__ void __launch_bounds__(256)
convert_act(const float* __restrict__ x, __half* __restrict__ y)
{
    size_t i = ((size_t)blockIdx.x * 256 + threadIdx.x) * 4;
    float4 v = *(const float4*)(x + i);
    __half2 p0 = __floats2half2_rn(v.x, v.y);
    __half2 p1 = __floats2half2_rn(v.z, v.w);
    *(uint2*)(y + i) = make_uint2(*(uint32_t*)&p0, *(uint32_t*)&p1);
}

// ---------------------------------------------------------------------------
// Transpose + round weights: Wt[n][k] = fp16(W[k][n]), 4 matrices (z-dim)
// ---------------------------------------------------------------------------
__global__ void __launch_bounds__(256)
transpose_w(const float* __restrict__ w0, const float* __restrict__ w1,
            const float* __restrict__ w2, const float* __restrict__ w3,
            __half* __restrict__ wt)
{
    __shared__ float t[32][33];
    const int z = blockIdx.z;
    const float* W = (z == 0) ? w0 : ((z == 1) ? w1 : ((z == 2) ? w2 : w3));
    const int n0 = blockIdx.x * 32, k0 = blockIdx.y * 32;
    const int tx = threadIdx.x & 31, ty = threadIdx.x >> 5;
#pragma unroll
    for (int r = 0; r < 4; r++)
        t[ty + r * 8][tx] = W[(size_t)(k0 + ty + r * 8) * HID + n0 + tx];
    __syncthreads();
    const size_t base = (size_t)z * HID * HID;
#pragma unroll
    for (int r = 0; r < 4; r++) {
        int n = n0 + ty + r * 8;
        int k = k0 + tx;
        wt[base + (size_t)n * HID + k] = __float2half_rn(t[tx][ty + r * 8]);
    }
}

// ---------------------------------------------------------------------------
// HMMA neighborhood attention.
// CTA = 128 queries of one (b,h); 8 warps x 16 rows.
// smem: Q[128][64], K[144][64], V[144][64] (rows s0-3..s0+130, clamped),
// pitch 144 B (128 data + 16 pad -> conflict-free ldsm, stride 36 banks).
// Warp w: S[16x32] = Q[16wx16..][64] x K-window[16w..16w+31][64]^T via HMMA,
// mask to 7-tap band, softmax per row (4-lane reductions), then P x V with
// score-accumulators reused directly as A-fragments and ldmatrix.trans on V.
// ---------------------------------------------------------------------------
#define PV      144
#define ASMEM   ((128 + 144 + 144) * PV)    // 59904

__global__ void __launch_bounds__(256, 1)
attn_mma(const __half* __restrict__ Q, const __half* __restrict__ K,
         const __half* __restrict__ V, __half* __restrict__ O)
{
    extern __shared__ char smem[];
    const uint32_t sbq = smem_u32(smem);
    const uint32_t sbk = sbq + 128 * PV;
    const uint32_t sbv = sbk + 144 * PV;
    const int tid = threadIdx.x, lane = tid & 31, w = tid >> 5;
    const int bh = blockIdx.x >> 6;              // 64 s-blocks per (b,h)
    const int s0 = (blockIdx.x & 63) * 128;
    const int b = bh >> 4, h = bh & 15;
    const size_t rowbase = ((size_t)b * SEQ) * HID + h * HDIM;

    // ---- stage Q/K/V ----
#pragma unroll
    for (int r = 0; r < 4; r++) {
        int idx = tid + r * 256;                 // 1024 = 128 rows x 8 chunks
        int row = idx >> 3, c = idx & 7;
        cp16(sbq + row * PV + c * 16,
             Q + rowbase + (size_t)(s0 + row) * HID + c * 8);
    }
    for (int idx = tid; idx < 1152; idx += 256) { // 144 rows x 8 chunks
        int row = idx >> 3, c = idx & 7;
        int sk = s0 + row - 3;
        sk = sk < 0 ? 0 : (sk >= SEQ ? SEQ - 1 : sk);
        cp16(sbk + row * PV + c * 16, K + rowbase + (size_t)sk * HID + c * 8);
        cp16(sbv + row * PV + c * 16, V + rowbase + (size_t)sk * HID + c * 8);
    }
    asm volatile("cp.async.commit_group;\n\tcp.async.wait_group 0;" ::: "memory");
    __syncthreads();

    const int mrow = lane >> 3, jrow = lane & 7;
    const int grp = lane >> 2, t4 = lane & 3;
    const uint32_t aq_off = sbq + (uint32_t)((w * 16 + (mrow & 1) * 8 + jrow) * PV
                                             + (mrow >> 1) * 16);
    const uint32_t bk_off = sbk + (uint32_t)((w * 16 + (mrow >> 1) * 8 + jrow) * PV
                                             + (mrow & 1) * 16);
    const uint32_t bv_off = sbv + (uint32_t)((w * 16 + (mrow & 1) * 8 + jrow) * PV
                                             + (mrow >> 1) * 16);

    // ---- S = Q K^T  (16x32 per warp) ----
    float accS[4][4];
#pragma unroll
    for (int i = 0; i < 4; i++)
#pragma unroll
        for (int r = 0; r < 4; r++) accS[i][r] = 0.0f;

#pragma unroll
    for (int ks = 0; ks < 4; ks++) {
        uint32_t aq[4], bk0[4], bk1[4];
        ldsm_x4(aq,  aq_off + ks * 32);
        ldsm_x4(bk0, bk_off + ks * 32);
        ldsm_x4(bk1, bk_off + 16 * PV + ks * 32);
        mma16816(accS[0], aq, &bk0[0]);
        mma16816(accS[1], aq, &bk0[2]);
        mma16816(accS[2], aq, &bk1[0]);
        mma16816(accS[3], aq, &bk1[2]);
    }

    // ---- mask to 7-tap band + scale ----
    const float NEG = -1e30f;
#pragma unroll
    for (int ni = 0; ni < 4; ni++)
#pragma unroll
        for (int pp = 0; pp < 4; pp++) {
            int r = (pp >= 2) ? grp + 8 : grp;
            int c = 8 * ni + 2 * t4 + (pp & 1);
            int sk = s0 + 16 * w + c - 3;
            bool ok = (c >= r) && (c <= r + 6) && (sk >= 0) && (sk < SEQ);
            accS[ni][pp] = ok ? accS[ni][pp] * ATT_SCALE : NEG;
        }

    // ---- softmax per row (rows grp and grp+8; reduce over 4 lanes) ----
    float m0 = NEG, m1 = NEG;
#pragma unroll
    for (int ni = 0; ni < 4; ni++) {
        m0 = fmaxf(m0, fmaxf(accS[ni][0], accS[ni][1]));
        m1 = fmaxf(m1, fmaxf(accS[ni][2], accS[ni][3]));
    }
#pragma unroll
    for (int o = 1; o <= 2; o <<= 1) {
        m0 = fmaxf(m0, __shfl_xor_sync(0xffffffffu, m0, o));
        m1 = fmaxf(m1, __shfl_xor_sync(0xffffffffu, m1, o));
    }
    float d0 = 0.0f, d1 = 0.0f;
#pragma unroll
    for (int ni = 0; ni < 4; ni++) {
        accS[ni][0] = __expf(accS[ni][0] - m0);
        accS[ni][1] = __expf(accS[ni][1] - m0);
        accS[ni][2] = __expf(accS[ni][2] - m1);
        accS[ni][3] = __expf(accS[ni][3] - m1);
        d0 += accS[ni][0] + accS[ni][1];
        d1 += accS[ni][2] + accS[ni][3];
    }
#pragma unroll
    for (int o = 1; o <= 2; o <<= 1) {
        d0 += __shfl_xor_sync(0xffffffffu, d0, o);
        d1 += __shfl_xor_sync(0xffffffffu, d1, o);
    }
    const float inv0 = 1.0f / d0, inv1 = 1.0f / d1;

    // ---- P fragments: reuse accS layout as m16n8k16 A operand ----
    uint32_t aP[2][4];
#pragma unroll
    for (int ks = 0; ks < 2; ks++) {
        __half2 v0 = __floats2half2_rn(accS[2 * ks][0] * inv0,
                                       accS[2 * ks][1] * inv0);
        __half2 v1 = __floats2half2_rn(accS[2 * ks][2] * inv1,
                                       accS[2 * ks][3] * inv1);
        __half2 v2 = __floats2half2_rn(accS[2 * ks + 1][0] * inv0,
                                       accS[2 * ks + 1][1] * inv0);
        __half2 v3 = __floats2half2_rn(accS[2 * ks + 1][2] * inv1,
                                       accS[2 * ks + 1][3] * inv1);
        aP[ks][0] = *(uint32_t*)&v0;
        aP[ks][1] = *(uint32_t*)&v1;
        aP[ks][2] = *(uint32_t*)&v2;
        aP[ks][3] = *(uint32_t*)&v3;
    }

    // ---- O = P x V  (16x64 per warp) ----
    float accO[8][4];
#pragma unroll
    for (int i = 0; i < 8; i++)
#pragma unroll
        for (int r = 0; r < 4; r++) accO[i][r] = 0.0f;

#pragma unroll
    for (int g = 0; g < 4; g++)
#pragma unroll
        for (int ks = 0; ks < 2; ks++) {
            uint32_t bv[4];
            ldsm_x4_t(bv, bv_off + ks * 16 * PV + g * 32);
            mma16816(accO[2 * g],     aP[ks], &bv[0]);
            mma16816(accO[2 * g + 1], aP[ks], &bv[2]);
        }

    // ---- store fp16 ----
    const int q0 = s0 + 16 * w;
#pragma unroll
    for (int nf = 0; nf < 8; nf++) {
        int col = 8 * nf + 2 * t4;
        __half2 p0 = __floats2half2_rn(accO[nf][0], accO[nf][1]);
        __half2 p1 = __floats2half2_rn(accO[nf][2], accO[nf][3]);
        *(uint32_t*)(O + rowbase + (size_t)(q0 + grp) * HID + col)     = *(uint32_t*)&p0;
        *(uint32_t*)(O + rowbase + (size_t)(q0 + grp + 8) * HID + col) = *(uint32_t*)&p1;
    }
}

// ---------------------------------------------------------------------------
// Launch
// ---------------------------------------------------------------------------
extern "C" void kernel_launch(void* const* d_in, const int* in_sizes, int n_in,
                              void* d_out, int out_size)
{
    const float* hs  = (const float*)d_in[0];
    const float* w_q = (const float*)d_in[1];
    const float* b_q = (const float*)d_in[2];
    const float* w_k = (const float*)d_in[3];
    const float* b_k = (const float*)d_in[4];
    const float* w_v = (const float*)d_in[5];
    const float* b_v = (const float*)d_in[6];
    const float* w_o = (const float*)d_in[7];
    const float* b_o = (const float*)d_in[8];
    float* out = (float*)d_out;

    __half *qb, *kb, *vb, *ab, *wt;
    cudaGetSymbolAddress((void**)&qb, g_q);
    cudaGetSymbolAddress((void**)&kb, g_k);
    cudaGetSymbolAddress((void**)&vb, g_v);
    cudaGetSymbolAddress((void**)&ab, g_a);
    cudaGetSymbolAddress((void**)&wt, g_w);

    cudaFuncSetAttribute(gemm_mma<true>,
                         cudaFuncAttributeMaxDynamicSharedMemorySize, SMEMB);
    cudaFuncSetAttribute(gemm_mma<false>,
                         cudaFuncAttributeMaxDynamicSharedMemorySize, SMEMB);
    cudaFuncSetAttribute(attn_mma,
                         cudaFuncAttributeMaxDynamicSharedMemorySize, ASMEM);

    const int act_blocks = (M_ROWS * HID) / (256 * 4);   // 16384

    // 1) convert activations to fp16; transpose+round weights
    convert_act<<<act_blocks, 256>>>(hs, ab);
    transpose_w<<<dim3(32, 32, 4), 256>>>(w_q, w_k, w_v, w_o, wt);

    // 2) fused QKV GEMM: 3 matrices x 4 N-tiles(256) x 128 M-tiles -> fp16
    gemm_mma<true><<<dim3(12, 128), 512, SMEMB>>>(
        ab, wt, 0, b_q, b_k, b_v, qb, kb, vb);

    // 3) HMMA neighborhood attention (fp16 in, fp16 out into A operand)
    attn_mma<<<BATCH * NHEADS * (SEQ / 128), 256, ASMEM>>>(qb, kb, vb, ab);

    // 4) O projection -> fp32 output
    gemm_mma<false><<<dim3(4, 128), 512, SMEMB>>>(
        ab, wt, 3, b_o, b_o, b_o, out, out, out);
}

// round 12
// speedup vs baseline: 2.3857x; 1.0063x over previous
#include <cuda_runtime.h>
#include <cuda_fp16.h>
#include <math.h>
#include <stdint.h>

// ---------------------------------------------------------------------------
// Problem constants
// ---------------------------------------------------------------------------
#define BATCH     2
#define SEQ       8192
#define HID       1024
#define NHEADS    16
#define HDIM      64
#define KWIN      7
#define ATT_SCALE 0.125f
#define M_ROWS    (BATCH * SEQ)     // 16384

// ---------------------------------------------------------------------------
// Scratch (__device__ globals: allowed, no runtime allocation)
// ---------------------------------------------------------------------------
__device__ __half g_q[(size_t)M_ROWS * HID];
__device__ __half g_k[(size_t)M_ROWS * HID];
__device__ __half g_v[(size_t)M_ROWS * HID];
__device__ __half g_a[(size_t)M_ROWS * HID];      // fp16 A operand (reused)
__device__ __half g_w[(size_t)4 * HID * HID];     // transposed [n][k], fp16

// ---------------------------------------------------------------------------
// PTX helpers (base sm_103 target — NO 'a'-gated features)
// ---------------------------------------------------------------------------
__device__ __forceinline__ uint32_t smem_u32(const void* p) {
    uint32_t a;
    asm("{ .reg .u64 t; cvta.to.shared.u64 t, %1; cvt.u32.u64 %0, t; }"
        : "=r"(a) : "l"(p));
    return a;
}
__device__ __forceinline__ void cp16(uint32_t s, const void* g) {
    asm volatile("cp.async.cg.shared.global [%0], [%1], 16;"
                 :: "r"(s), "l"(g));
}
__device__ __forceinline__ void ldsm_x4(uint32_t* r, uint32_t addr) {
    asm volatile("ldmatrix.sync.aligned.m8n8.x4.shared.b16 {%0,%1,%2,%3}, [%4];"
                 : "=r"(r[0]), "=r"(r[1]), "=r"(r[2]), "=r"(r[3]) : "r"(addr));
}
__device__ __forceinline__ void ldsm_x4_t(uint32_t* r, uint32_t addr) {
    asm volatile("ldmatrix.sync.aligned.m8n8.x4.trans.shared.b16 {%0,%1,%2,%3}, [%4];"
                 : "=r"(r[0]), "=r"(r[1]), "=r"(r[2]), "=r"(r[3]) : "r"(addr));
}
__device__ __forceinline__ void mma16816(float* d, const uint32_t* a,
                                         const uint32_t* b) {
    asm volatile(
        "mma.sync.aligned.m16n8k16.row.col.f32.f16.f16.f32 "
        "{%0,%1,%2,%3}, {%4,%5,%6,%7}, {%8,%9}, {%0,%1,%2,%3};"
        : "+f"(d[0]), "+f"(d[1]), "+f"(d[2]), "+f"(d[3])
        : "r"(a[0]), "r"(a[1]), "r"(a[2]), "r"(a[3]), "r"(b[0]), "r"(b[1]));
}

// ---------------------------------------------------------------------------
// GEMM config: 128x256 CTA tile, BK=32, 4-stage cp.async ring, 512 threads
// (unchanged from R10/R11 — verified)
// ---------------------------------------------------------------------------
#define PITCH   80
#define TILE_A  (128 * PITCH)
#define TILE_B  (256 * PITCH)
#define OFF_B   TILE_A
#define BUFB    (TILE_A + TILE_B)
#define NSTAGE  4
#define SMEMB   (NSTAGE * BUFB)         // 122880

__device__ __forceinline__ void load_chunk(
    uint32_t base, int tid, int k0, int m0, int n0,
    const __half* __restrict__ A, const __half* __restrict__ B)
{
    {
        int row = tid >> 2, c = tid & 3;
        uint32_t so = (uint32_t)(row * PITCH + c * 16);
        size_t go = (size_t)(m0 + row) * HID + k0 + c * 8;
        cp16(base + so, A + go);
    }
#pragma unroll
    for (int r = 0; r < 2; r++) {
        int idx = tid + r * 512;
        int row = idx >> 2, c = idx & 3;
        uint32_t so = (uint32_t)(row * PITCH + c * 16);
        size_t go = (size_t)(n0 + row) * HID + k0 + c * 8;
        cp16(base + OFF_B + so, B + go);
    }
    asm volatile("cp.async.commit_group;" ::: "memory");
}

template <bool HALF_OUT>
__global__ void __launch_bounds__(512, 1)
gemm_mma(const __half* __restrict__ A, const __half* __restrict__ W,
         int mat_base,
         const float* __restrict__ bias0, const float* __restrict__ bias1,
         const float* __restrict__ bias2,
         void* __restrict__ c0v, void* __restrict__ c1v, void* __restrict__ c2v)
{
    extern __shared__ char smem[];
    const uint32_t sb = smem_u32(smem);
    const int tid  = threadIdx.x;
    const int lane = tid & 31;
    const int wid  = tid >> 5;
    const int wm   = wid >> 3;
    const int wn   = wid & 7;
    const int mi_  = blockIdx.x >> 2;
    const int n0   = (blockIdx.x & 3) * 256;
    const int m0   = blockIdx.y * 128;

    const __half* B = W + (size_t)(mat_base + mi_) * HID * HID;
    const float* bias = (mi_ == 0) ? bias0 : ((mi_ == 1) ? bias1 : bias2);
    void* Cv = (mi_ == 0) ? c0v : ((mi_ == 1) ? c1v : c2v);

    float acc[4][4][4];
#pragma unroll
    for (int i = 0; i < 4; i++)
#pragma unroll
        for (int j = 0; j < 4; j++)
#pragma unroll
            for (int r = 0; r < 4; r++) acc[i][j][r] = 0.0f;

    load_chunk(sb,            tid, 0,  m0, n0, A, B);
    load_chunk(sb + BUFB,     tid, 32, m0, n0, A, B);
    load_chunk(sb + 2 * BUFB, tid, 64, m0, n0, A, B);

    const int mrow = lane >> 3;
    const int jrow = lane & 7;
    const uint32_t a_off = (uint32_t)((wm * 64 + (mrow & 1) * 8 + jrow) * PITCH
                                      + (mrow >> 1) * 16);
    const uint32_t b_off = (uint32_t)((wn * 32 + (mrow >> 1) * 8 + jrow) * PITCH
                                      + (mrow & 1) * 16) + OFF_B;

    const int NCHUNK = HID / 32;
    int st = 0;

    for (int ck = 0; ck < NCHUNK; ck++) {
        if (ck <= NCHUNK - 3)      asm volatile("cp.async.wait_group 2;" ::: "memory");
        else if (ck == NCHUNK - 2) asm volatile("cp.async.wait_group 1;" ::: "memory");
        else                       asm volatile("cp.async.wait_group 0;" ::: "memory");
        __syncthreads();

        if (ck + 3 < NCHUNK) {
            int ls = st + 3; if (ls >= NSTAGE) ls -= NSTAGE;
            load_chunk(sb + ls * BUFB, tid, (ck + 3) * 32, m0, n0, A, B);
        }

        const uint32_t base = sb + st * BUFB;
#pragma unroll
        for (int ks = 0; ks < 2; ks++) {
            const uint32_t kb = ks * 32;
            uint32_t bf[2][4];
#pragma unroll
            for (int nj = 0; nj < 2; nj++)
                ldsm_x4(bf[nj], base + b_off + nj * 16 * PITCH + kb);
#pragma unroll
            for (int mi = 0; mi < 4; mi++) {
                uint32_t ah[4];
                ldsm_x4(ah, base + a_off + mi * 16 * PITCH + kb);
#pragma unroll
                for (int ni = 0; ni < 4; ni++)
                    mma16816(acc[mi][ni], ah, &bf[ni >> 1][(ni & 1) * 2]);
            }
        }
        if (++st == NSTAGE) st = 0;
    }

    const int grp = lane >> 2, t4 = lane & 3;
#pragma unroll
    for (int ni = 0; ni < 4; ni++) {
        const int col = n0 + wn * 32 + ni * 8 + t4 * 2;
        const float bv0 = bias[col], bv1 = bias[col + 1];
#pragma unroll
        for (int mi = 0; mi < 4; mi++) {
            const int r0 = m0 + wm * 64 + mi * 16 + grp;
            if (HALF_OUT) {
                __half* C = (__half*)Cv;
                __half2 p0 = __floats2half2_rn(acc[mi][ni][0] + bv0,
                                               acc[mi][ni][1] + bv1);
                __half2 p1 = __floats2half2_rn(acc[mi][ni][2] + bv0,
                                               acc[mi][ni][3] + bv1);
                *(uint32_t*)(C + (size_t)r0 * HID + col)       = *(uint32_t*)&p0;
                *(uint32_t*)(C + (size_t)(r0 + 8) * HID + col) = *(uint32_t*)&p1;
            } else {
                float* C = (float*)Cv;
                *(float2*)(C + (size_t)r0 * HID + col) =
                    make_float2(acc[mi][ni][0] + bv0, acc[mi][ni][1] + bv1);
                *(float2*)(C + (size_t)(r0 + 8) * HID + col) =
                    make_float2(acc[mi][ni][2] + bv0, acc[mi][ni][3] + bv1);
            }
        }
    }
}

// ---------------------------------------------------------------------------
// Fused prep: blocks [0,16384) convert activations fp32->fp16;
// blocks [16384,20480) transpose+round the 4 weight matrices.
// Independent work in one launch -> runs concurrently.
// ---------------------------------------------------------------------------
#define CONV_BLOCKS 16384
#define PREP_BLOCKS (CONV_BLOCKS + 4096)

__global__ void __launch_bounds__(256)
prep_kernel(const float* __restrict__ x, __half* __restrict__ y,
            const float* __restrict__ w0, const float* __restrict__ w1,
            const float* __restrict__ w2, const float* __restrict__ w3,
            __half* __restrict__ wt)
{
    __shared__ float t[32][33];
    if (blockIdx.x < CONV_BLOCKS) {
        size_t i = ((size_t)blockIdx.x * 256 + threadIdx.x) * 4;
        float4 v = *(const float4*)(x + i);
        __half2 p0 = __floats2half2_rn(v.x, v.y);
        __half2 p1 = __floats2half2_rn(v.z, v.w);
        *(uint2*)(y + i) = make_uint2(*(uint32_t*)&p0, *(uint32_t*)&p1);
    } else {
        const int bid = blockIdx.x - CONV_BLOCKS;      // 0..4095
        const int z = bid >> 10;                       // matrix
        const int rem = bid & 1023;
        const int n0 = (rem & 31) * 32, k0 = (rem >> 5) * 32;
        const float* W = (z == 0) ? w0 : ((z == 1) ? w1 : ((z == 2) ? w2 : w3));
        const int tx = threadIdx.x & 31, ty = threadIdx.x >> 5;   // 32 x 8
#pragma unroll
        for (int r = 0; r < 4; r++)
            t[ty + r * 8][tx] = W[(size_t)(k0 + ty + r * 8) * HID + n0 + tx];
        __syncthreads();
        const size_t base = (size_t)z * HID * HID;
#pragma unroll
        for (int r = 0; r < 4; r++) {
            int n = n0 + ty + r * 8;
            int k = k0 + tx;
            wt[base + (size_t)n * HID + k] = __float2half_rn(t[tx][ty + r * 8]);
        }
    }
}

// ---------------------------------------------------------------------------
// HMMA neighborhood attention (two-group staging: Q+K first, V second,
// so S/softmax overlaps the in-flight V load).
// CTA = 128 queries of one (b,h); 8 warps x 16 rows.
// ---------------------------------------------------------------------------
#define PV      144
#define ASMEM   ((128 + 144 + 144) * PV)    // 59904

__global__ void __launch_bounds__(256)
attn_mma(const __half* __restrict__ Q, const __half* __restrict__ K,
         const __half* __restrict__ V, __half* __restrict__ O)
{
    extern __shared__ char smem[];
    const uint32_t sbq = smem_u32(smem);
    const uint32_t sbk = sbq + 128 * PV;
    const uint32_t sbv = sbk + 144 * PV;
    const int tid = threadIdx.x, lane = tid & 31, w = tid >> 5;
    const int bh = blockIdx.x >> 6;
    const int s0 = (blockIdx.x & 63) * 128;
    const int b = bh >> 4, h = bh & 15;
    const size_t rowbase = ((size_t)b * SEQ) * HID + h * HDIM;

    // ---- group 0: Q + K ----
#pragma unroll
    for (int r = 0; r < 4; r++) {
        int idx = tid + r * 256;
        int row = idx >> 3, c = idx & 7;
        cp16(sbq + row * PV + c * 16,
             Q + rowbase + (size_t)(s0 + row) * HID + c * 8);
    }
    for (int idx = tid; idx < 1152; idx += 256) {
        int row = idx >> 3, c = idx & 7;
        int sk = s0 + row - 3;
        sk = sk < 0 ? 0 : (sk >= SEQ ? SEQ - 1 : sk);
        cp16(sbk + row * PV + c * 16, K + rowbase + (size_t)sk * HID + c * 8);
    }
    asm volatile("cp.async.commit_group;" ::: "memory");
    // ---- group 1: V (overlaps S compute) ----
    for (int idx = tid; idx < 1152; idx += 256) {
        int row = idx >> 3, c = idx & 7;
        int sk = s0 + row - 3;
        sk = sk < 0 ? 0 : (sk >= SEQ ? SEQ - 1 : sk);
        cp16(sbv + row * PV + c * 16, V + rowbase + (size_t)sk * HID + c * 8);
    }
    asm volatile("cp.async.commit_group;" ::: "memory");
    asm volatile("cp.async.wait_group 1;" ::: "memory");   // Q+K ready
    __syncthreads();

    const int mrow = lane >> 3, jrow = lane & 7;
    const int grp = lane >> 2, t4 = lane & 3;
    const uint32_t aq_off = sbq + (uint32_t)((w * 16 + (mrow & 1) * 8 + jrow) * PV
                                             + (mrow >> 1) * 16);
    const uint32_t bk_off = sbk + (uint32_t)((w * 16 + (mrow >> 1) * 8 + jrow) * PV
                                             + (mrow & 1) * 16);
    const uint32_t bv_off = sbv + (uint32_t)((w * 16 + (mrow & 1) * 8 + jrow) * PV
                                             + (mrow >> 1) * 16);

    // ---- S = Q K^T ----
    float accS[4][4];
#pragma unroll
    for (int i = 0; i < 4; i++)
#pragma unroll
        for (int r = 0; r < 4; r++) accS[i][r] = 0.0f;

#pragma unroll
    for (int ks = 0; ks < 4; ks++) {
        uint32_t aq[4], bk0[4], bk1[4];
        ldsm_x4(aq,  aq_off + ks * 32);
        ldsm_x4(bk0, bk_off + ks * 32);
        ldsm_x4(bk1, bk_off + 16 * PV + ks * 32);
        mma16816(accS[0], aq, &bk0[0]);
        mma16816(accS[1], aq, &bk0[2]);
        mma16816(accS[2], aq, &bk1[0]);
        mma16816(accS[3], aq, &bk1[2]);
    }

    // ---- mask + scale ----
    const float NEG = -1e30f;
#pragma unroll
    for (int ni = 0; ni < 4; ni++)
#pragma unroll
        for (int pp = 0; pp < 4; pp++) {
            int r = (pp >= 2) ? grp + 8 : grp;
            int c = 8 * ni + 2 * t4 + (pp & 1);
            int sk = s0 + 16 * w + c - 3;
            bool ok = (c >= r) && (c <= r + 6) && (sk >= 0) && (sk < SEQ);
            accS[ni][pp] = ok ? accS[ni][pp] * ATT_SCALE : NEG;
        }

    // ---- softmax (rows grp, grp+8; reduce over 4 lanes) ----
    float m0 = NEG, m1 = NEG;
#pragma unroll
    for (int ni = 0; ni < 4; ni++) {
        m0 = fmaxf(m0, fmaxf(accS[ni][0], accS[ni][1]));
        m1 = fmaxf(m1, fmaxf(accS[ni][2], accS[ni][3]));
    }
#pragma unroll
    for (int o = 1; o <= 2; o <<= 1) {
        m0 = fmaxf(m0, __shfl_xor_sync(0xffffffffu, m0, o));
        m1 = fmaxf(m1, __shfl_xor_sync(0xffffffffu, m1, o));
    }
    float d0 = 0.0f, d1 = 0.0f;
#pragma unroll
    for (int ni = 0; ni < 4; ni++) {
        accS[ni][0] = __expf(accS[ni][0] - m0);
        accS[ni][1] = __expf(accS[ni][1] - m0);
        accS[ni][2] = __expf(accS[ni][2] - m1);
        accS[ni][3] = __expf(accS[ni][3] - m1);
        d0 += accS[ni][0] + accS[ni][1];
        d1 += accS[ni][2] + accS[ni][3];
    }
#pragma unroll
    for (int o = 1; o <= 2; o <<= 1) {
        d0 += __shfl_xor_sync(0xffffffffu, d0, o);
        d1 += __shfl_xor_sync(0xffffffffu, d1, o);
    }
    const float inv0 = 1.0f / d0, inv1 = 1.0f / d1;

    // ---- P fragments ----
    uint32_t aP[2][4];
#pragma unroll
    for (int ks = 0; ks < 2; ks++) {
        __half2 v0 = __floats2half2_rn(accS[2 * ks][0] * inv0,
                                       accS[2 * ks][1] * inv0);
        __half2 v1 = __floats2half2_rn(accS[2 * ks][2] * inv1,
                                       accS[2 * ks][3] * inv1);
        __half2 v2 = __floats2half2_rn(accS[2 * ks + 1][0] * inv0,
                                       accS[2 * ks + 1][1] * inv0);
        __half2 v3 = __floats2half2_rn(accS[2 * ks + 1][2] * inv1,
                                       accS[2 * ks + 1][3] * inv1);
        aP[ks][0] = *(uint32_t*)&v0;
        aP[ks][1] = *(uint32_t*)&v1;
        aP[ks][2] = *(uint32_t*)&v2;
        aP[ks][3] = *(uint32_t*)&v3;
    }

    // ---- wait for V, then O = P x V ----
    asm volatile("cp.async.wait_group 0;" ::: "memory");
    __syncthreads();

    float accO[8][4];
#pragma unroll
    for (int i = 0; i < 8; i++)
#pragma unroll
        for (int r = 0; r < 4; r++) accO[i][r] = 0.0f;

#pragma unroll
    for (int g = 0; g < 4; g++)
#pragma unroll
        for (int ks = 0; ks < 2; ks++) {
            uint32_t bv[4];
            ldsm_x4_t(bv, bv_off + ks * 16 * PV + g * 32);
            mma16816(accO[2 * g],     aP[ks], &bv[0]);
            mma16816(accO[2 * g + 1], aP[ks], &bv[2]);
        }

    // ---- store fp16 ----
    const int q0 = s0 + 16 * w;
#pragma unroll
    for (int nf = 0; nf < 8; nf++) {
        int col = 8 * nf + 2 * t4;
        __half2 p0 = __floats2half2_rn(accO[nf][0], accO[nf][1]);
        __half2 p1 = __floats2half2_rn(accO[nf][2], accO[nf][3]);
        *(uint32_t*)(O + rowbase + (size_t)(q0 + grp) * HID + col)     = *(uint32_t*)&p0;
        *(uint32_t*)(O + rowbase + (size_t)(q0 + grp + 8) * HID + col) = *(uint32_t*)&p1;
    }
}

// ---------------------------------------------------------------------------
// Launch
// ---------------------------------------------------------------------------
extern "C" void kernel_launch(void* const* d_in, const int* in_sizes, int n_in,
                              void* d_out, int out_size)
{
    const float* hs  = (const float*)d_in[0];
    const float* w_q = (const float*)d_in[1];
    const float* b_q = (const float*)d_in[2];
    const float* w_k = (const float*)d_in[3];
    const float* b_k = (const float*)d_in[4];
    const float* w_v = (const float*)d_in[5];
    const float* b_v = (const float*)d_in[6];
    const float* w_o = (const float*)d_in[7];
    const float* b_o = (const float*)d_in[8];
    float* out = (float*)d_out;

    __half *qb, *kb, *vb, *ab, *wt;
    cudaGetSymbolAddress((void**)&qb, g_q);
    cudaGetSymbolAddress((void**)&kb, g_k);
    cudaGetSymbolAddress((void**)&vb, g_v);
    cudaGetSymbolAddress((void**)&ab, g_a);
    cudaGetSymbolAddress((void**)&wt, g_w);

    cudaFuncSetAttribute(gemm_mma<true>,
                         cudaFuncAttributeMaxDynamicSharedMemorySize, SMEMB);
    cudaFuncSetAttribute(gemm_mma<false>,
                         cudaFuncAttributeMaxDynamicSharedMemorySize, SMEMB);
    cudaFuncSetAttribute(attn_mma,
                         cudaFuncAttributeMaxDynamicSharedMemorySize, ASMEM);

    // 1) fused prep: activation convert + weight transpose (one launch)
    prep_kernel<<<PREP_BLOCKS, 256>>>(hs, ab, w_q, w_k, w_v, w_o, wt);

    // 2) fused QKV GEMM: 3 matrices x 4 N-tiles(256) x 128 M-tiles -> fp16
    gemm_mma<true><<<dim3(12, 128), 512, SMEMB>>>(
        ab, wt, 0, b_q, b_k, b_v, qb, kb, vb);

    // 3) HMMA neighborhood attention (fp16 in, fp16 out into A operand)
    attn_mma<<<BATCH * NHEADS * (SEQ / 128), 256, ASMEM>>>(qb, kb, vb, ab);

    // 4) O projection -> fp32 output
    gemm_mma<false><<<dim3(4, 128), 512, SMEMB>>>(
        ab, wt, 3, b_o, b_o, b_o, out, out, out);
}

// round 13
// speedup vs baseline: 2.7094x; 1.1356x over previous
#include <cuda_runtime.h>
#include <cuda_fp16.h>
#include <math.h>
#include <stdint.h>

// ---------------------------------------------------------------------------
// Problem constants
// ---------------------------------------------------------------------------
#define BATCH     2
#define SEQ       8192
#define HID       1024
#define NHEADS    16
#define HDIM      64
#define KWIN      7
#define ATT_SCALE 0.125f
#define M_ROWS    (BATCH * SEQ)     // 16384

// ---------------------------------------------------------------------------
// Scratch (__device__ globals: allowed, no runtime allocation)
// ---------------------------------------------------------------------------
__device__ __half g_q[(size_t)M_ROWS * HID];
__device__ __half g_k[(size_t)M_ROWS * HID];
__device__ __half g_v[(size_t)M_ROWS * HID];
__device__ __half g_a[(size_t)M_ROWS * HID];      // fp16 A operand (reused)
__device__ __half g_w[(size_t)4 * HID * HID];     // transposed [n][k], fp16

// ---------------------------------------------------------------------------
// PTX helpers (base sm_103 target — NO 'a'-gated features)
// ---------------------------------------------------------------------------
__device__ __forceinline__ uint32_t smem_u32(const void* p) {
    uint32_t a;
    asm("{ .reg .u64 t; cvta.to.shared.u64 t, %1; cvt.u32.u64 %0, t; }"
        : "=r"(a) : "l"(p));
    return a;
}
__device__ __forceinline__ void cp16(uint32_t s, const void* g) {
    asm volatile("cp.async.cg.shared.global [%0], [%1], 16;"
                 :: "r"(s), "l"(g));
}
__device__ __forceinline__ void ldsm_x4(uint32_t* r, uint32_t addr) {
    asm volatile("ldmatrix.sync.aligned.m8n8.x4.shared.b16 {%0,%1,%2,%3}, [%4];"
                 : "=r"(r[0]), "=r"(r[1]), "=r"(r[2]), "=r"(r[3]) : "r"(addr));
}
__device__ __forceinline__ void ldsm_x4_t(uint32_t* r, uint32_t addr) {
    asm volatile("ldmatrix.sync.aligned.m8n8.x4.trans.shared.b16 {%0,%1,%2,%3}, [%4];"
                 : "=r"(r[0]), "=r"(r[1]), "=r"(r[2]), "=r"(r[3]) : "r"(addr));
}
__device__ __forceinline__ void mma16816(float* d, const uint32_t* a,
                                         const uint32_t* b) {
    asm volatile(
        "mma.sync.aligned.m16n8k16.row.col.f32.f16.f16.f32 "
        "{%0,%1,%2,%3}, {%4,%5,%6,%7}, {%8,%9}, {%0,%1,%2,%3};"
        : "+f"(d[0]), "+f"(d[1]), "+f"(d[2]), "+f"(d[3])
        : "r"(a[0]), "r"(a[1]), "r"(a[2]), "r"(a[3]), "r"(b[0]), "r"(b[1]));
}

// ---------------------------------------------------------------------------
// GEMM config: 128x128 CTA tile, BK=32, 4-stage cp.async ring, 256 threads,
// 2 CTAs per SM (barrier phases of the two CTAs interleave).
// Warp-level code identical to the verified R10-R12 64x32 warp tile.
// ---------------------------------------------------------------------------
#define PITCH   80
#define TILE_A  (128 * PITCH)           // 10240
#define OFF_B   TILE_A
#define BUFB    (2 * TILE_A)            // 20480 per stage (A + B)
#define NSTAGE  4
#define SMEMB   (NSTAGE * BUFB)         // 81920

__device__ __forceinline__ void load_chunk(
    uint32_t base, int tid, int k0, int m0, int n0,
    const __half* __restrict__ A, const __half* __restrict__ B)
{
#pragma unroll
    for (int r = 0; r < 2; r++) {   // A: 128 rows x 64B = 512 cp16
        int idx = tid + r * 256;
        int row = idx >> 2, c = idx & 3;
        uint32_t so = (uint32_t)(row * PITCH + c * 16);
        size_t go = (size_t)(m0 + row) * HID + k0 + c * 8;
        cp16(base + so, A + go);
    }
#pragma unroll
    for (int r = 0; r < 2; r++) {   // B: 128 rows x 64B = 512 cp16
        int idx = tid + r * 256;
        int row = idx >> 2, c = idx & 3;
        uint32_t so = (uint32_t)(row * PITCH + c * 16);
        size_t go = (size_t)(n0 + row) * HID + k0 + c * 8;
        cp16(base + OFF_B + so, B + go);
    }
    asm volatile("cp.async.commit_group;" ::: "memory");
}

// C[m][n] = sum_k A[m][k]*Wt[n][k] + bias[n], single-pass fp16 HMMA.
// grid.x: (matrix_within_launch << 3) | n_tile;  grid.y: m_tile
template <bool HALF_OUT>
__global__ void __launch_bounds__(256, 2)
gemm_mma(const __half* __restrict__ A, const __half* __restrict__ W,
         int mat_base,
         const float* __restrict__ bias0, const float* __restrict__ bias1,
         const float* __restrict__ bias2,
         void* __restrict__ c0v, void* __restrict__ c1v, void* __restrict__ c2v)
{
    extern __shared__ char smem[];
    const uint32_t sb = smem_u32(smem);
    const int tid  = threadIdx.x;
    const int lane = tid & 31;
    const int wid  = tid >> 5;          // 0..7
    const int wm   = wid >> 2;          // 0..1 -> 64-row slab
    const int wn   = wid & 3;           // 0..3 -> 32-col slab
    const int mi_  = blockIdx.x >> 3;   // matrix within launch
    const int n0   = (blockIdx.x & 7) * 128;
    const int m0   = blockIdx.y * 128;

    const __half* B = W + (size_t)(mat_base + mi_) * HID * HID;
    const float* bias = (mi_ == 0) ? bias0 : ((mi_ == 1) ? bias1 : bias2);
    void* Cv = (mi_ == 0) ? c0v : ((mi_ == 1) ? c1v : c2v);

    float acc[4][4][4];
#pragma unroll
    for (int i = 0; i < 4; i++)
#pragma unroll
        for (int j = 0; j < 4; j++)
#pragma unroll
            for (int r = 0; r < 4; r++) acc[i][j][r] = 0.0f;

    load_chunk(sb,            tid, 0,  m0, n0, A, B);
    load_chunk(sb + BUFB,     tid, 32, m0, n0, A, B);
    load_chunk(sb + 2 * BUFB, tid, 64, m0, n0, A, B);

    const int mrow = lane >> 3;
    const int jrow = lane & 7;
    const uint32_t a_off = (uint32_t)((wm * 64 + (mrow & 1) * 8 + jrow) * PITCH
                                      + (mrow >> 1) * 16);
    const uint32_t b_off = (uint32_t)((wn * 32 + (mrow >> 1) * 8 + jrow) * PITCH
                                      + (mrow & 1) * 16) + OFF_B;

    const int NCHUNK = HID / 32;        // 32
    int st = 0;

    for (int ck = 0; ck < NCHUNK; ck++) {
        if (ck <= NCHUNK - 3)      asm volatile("cp.async.wait_group 2;" ::: "memory");
        else if (ck == NCHUNK - 2) asm volatile("cp.async.wait_group 1;" ::: "memory");
        else                       asm volatile("cp.async.wait_group 0;" ::: "memory");
        __syncthreads();

        if (ck + 3 < NCHUNK) {
            int ls = st + 3; if (ls >= NSTAGE) ls -= NSTAGE;
            load_chunk(sb + ls * BUFB, tid, (ck + 3) * 32, m0, n0, A, B);
        }

        const uint32_t base = sb + st * BUFB;
#pragma unroll
        for (int ks = 0; ks < 2; ks++) {
            const uint32_t kb = ks * 32;
            uint32_t bf[2][4];
#pragma unroll
            for (int nj = 0; nj < 2; nj++)
                ldsm_x4(bf[nj], base + b_off + nj * 16 * PITCH + kb);
#pragma unroll
            for (int mi = 0; mi < 4; mi++) {
                uint32_t ah[4];
                ldsm_x4(ah, base + a_off + mi * 16 * PITCH + kb);
#pragma unroll
                for (int ni = 0; ni < 4; ni++)
                    mma16816(acc[mi][ni], ah, &bf[ni >> 1][(ni & 1) * 2]);
            }
        }
        if (++st == NSTAGE) st = 0;
    }

    const int grp = lane >> 2, t4 = lane & 3;
#pragma unroll
    for (int ni = 0; ni < 4; ni++) {
        const int col = n0 + wn * 32 + ni * 8 + t4 * 2;
        const float bv0 = bias[col], bv1 = bias[col + 1];
#pragma unroll
        for (int mi = 0; mi < 4; mi++) {
            const int r0 = m0 + wm * 64 + mi * 16 + grp;
            if (HALF_OUT) {
                __half* C = (__half*)Cv;
                __half2 p0 = __floats2half2_rn(acc[mi][ni][0] + bv0,
                                               acc[mi][ni][1] + bv1);
                __half2 p1 = __floats2half2_rn(acc[mi][ni][2] + bv0,
                                               acc[mi][ni][3] + bv1);
                *(uint32_t*)(C + (size_t)r0 * HID + col)       = *(uint32_t*)&p0;
                *(uint32_t*)(C + (size_t)(r0 + 8) * HID + col) = *(uint32_t*)&p1;
            } else {
                float* C = (float*)Cv;
                *(float2*)(C + (size_t)r0 * HID + col) =
                    make_float2(acc[mi][ni][0] + bv0, acc[mi][ni][1] + bv1);
                *(float2*)(C + (size_t)(r0 + 8) * HID + col) =
                    make_float2(acc[mi][ni][2] + bv0, acc[mi][ni][3] + bv1);
            }
        }
    }
}

// ---------------------------------------------------------------------------
// Fused prep: blocks [0,16384) convert activations fp32->fp16;
// blocks [16384,20480) transpose+round the 4 weight matrices.
// ---------------------------------------------------------------------------
#define CONV_BLOCKS 16384
#define PREP_BLOCKS (CONV_BLOCKS + 4096)

__global__ void __launch_bounds__(256)
prep_kernel(const float* __restrict__ x, __half* __restrict__ y,
            const float* __restrict__ w0, const float* __restrict__ w1,
            const float* __restrict__ w2, const float* __restrict__ w3,
            __half* __restrict__ wt)
{
    __shared__ float t[32][33];
    if (blockIdx.x < CONV_BLOCKS) {
        size_t i = ((size_t)blockIdx.x * 256 + threadIdx.x) * 4;
        float4 v = *(const float4*)(x + i);
        __half2 p0 = __floats2half2_rn(v.x, v.y);
        __half2 p1 = __floats2half2_rn(v.z, v.w);
        *(uint2*)(y + i) = make_uint2(*(uint32_t*)&p0, *(uint32_t*)&p1);
    } else {
        const int bid = blockIdx.x - CONV_BLOCKS;
        const int z = bid >> 10;
        const int rem = bid & 1023;
        const int n0 = (rem & 31) * 32, k0 = (rem >> 5) * 32;
        const float* W = (z == 0) ? w0 : ((z == 1) ? w1 : ((z == 2) ? w2 : w3));
        const int tx = threadIdx.x & 31, ty = threadIdx.x >> 5;
#pragma unroll
        for (int r = 0; r < 4; r++)
            t[ty + r * 8][tx] = W[(size_t)(k0 + ty + r * 8) * HID + n0 + tx];
        __syncthreads();
        const size_t base = (size_t)z * HID * HID;
#pragma unroll
        for (int r = 0; r < 4; r++) {
            int n = n0 + ty + r * 8;
            int k = k0 + tx;
            wt[base + (size_t)n * HID + k] = __float2half_rn(t[tx][ty + r * 8]);
        }
    }
}

// ---------------------------------------------------------------------------
// HMMA neighborhood attention (two-group staging; unchanged from R12)
// ---------------------------------------------------------------------------
#define PV      144
#define ASMEM   ((128 + 144 + 144) * PV)    // 59904

__global__ void __launch_bounds__(256)
attn_mma(const __half* __restrict__ Q, const __half* __restrict__ K,
         const __half* __restrict__ V, __half* __restrict__ O)
{
    extern __shared__ char smem[];
    const uint32_t sbq = smem_u32(smem);
    const uint32_t sbk = sbq + 128 * PV;
    const uint32_t sbv = sbk + 144 * PV;
    const int tid = threadIdx.x, lane = tid & 31, w = tid >> 5;
    const int bh = blockIdx.x >> 6;
    const int s0 = (blockIdx.x & 63) * 128;
    const int b = bh >> 4, h = bh & 15;
    const size_t rowbase = ((size_t)b * SEQ) * HID + h * HDIM;

#pragma unroll
    for (int r = 0; r < 4; r++) {
        int idx = tid + r * 256;
        int row = idx >> 3, c = idx & 7;
        cp16(sbq + row * PV + c * 16,
             Q + rowbase + (size_t)(s0 + row) * HID + c * 8);
    }
    for (int idx = tid; idx < 1152; idx += 256) {
        int row = idx >> 3, c = idx & 7;
        int sk = s0 + row - 3;
        sk = sk < 0 ? 0 : (sk >= SEQ ? SEQ - 1 : sk);
        cp16(sbk + row * PV + c * 16, K + rowbase + (size_t)sk * HID + c * 8);
    }
    asm volatile("cp.async.commit_group;" ::: "memory");
    for (int idx = tid; idx < 1152; idx += 256) {
        int row = idx >> 3, c = idx & 7;
        int sk = s0 + row - 3;
        sk = sk < 0 ? 0 : (sk >= SEQ ? SEQ - 1 : sk);
        cp16(sbv + row * PV + c * 16, V + rowbase + (size_t)sk * HID + c * 8);
    }
    asm volatile("cp.async.commit_group;" ::: "memory");
    asm volatile("cp.async.wait_group 1;" ::: "memory");
    __syncthreads();

    const int mrow = lane >> 3, jrow = lane & 7;
    const int grp = lane >> 2, t4 = lane & 3;
    const uint32_t aq_off = sbq + (uint32_t)((w * 16 + (mrow & 1) * 8 + jrow) * PV
                                             + (mrow >> 1) * 16);
    const uint32_t bk_off = sbk + (uint32_t)((w * 16 + (mrow >> 1) * 8 + jrow) * PV
                                             + (mrow & 1) * 16);
    const uint32_t bv_off = sbv + (uint32_t)((w * 16 + (mrow & 1) * 8 + jrow) * PV
                                             + (mrow >> 1) * 16);

    float accS[4][4];
#pragma unroll
    for (int i = 0; i < 4; i++)
#pragma unroll
        for (int r = 0; r < 4; r++) accS[i][r] = 0.0f;

#pragma unroll
    for (int ks = 0; ks < 4; ks++) {
        uint32_t aq[4], bk0[4], bk1[4];
        ldsm_x4(aq,  aq_off + ks * 32);
        ldsm_x4(bk0, bk_off + ks * 32);
        ldsm_x4(bk1, bk_off + 16 * PV + ks * 32);
        mma16816(accS[0], aq, &bk0[0]);
        mma16816(accS[1], aq, &bk0[2]);
        mma16816(accS[2], aq, &bk1[0]);
        mma16816(accS[3], aq, &bk1[2]);
    }

    const float NEG = -1e30f;
#pragma unroll
    for (int ni = 0; ni < 4; ni++)
#pragma unroll
        for (int pp = 0; pp < 4; pp++) {
            int r = (pp >= 2) ? grp + 8 : grp;
            int c = 8 * ni + 2 * t4 + (pp & 1);
            int sk = s0 + 16 * w + c - 3;
            bool ok = (c >= r) && (c <= r + 6) && (sk >= 0) && (sk < SEQ);
            accS[ni][pp] = ok ? accS[ni][pp] * ATT_SCALE : NEG;
        }

    float m0 = NEG, m1 = NEG;
#pragma unroll
    for (int ni = 0; ni < 4; ni++) {
        m0 = fmaxf(m0, fmaxf(accS[ni][0], accS[ni][1]));
        m1 = fmaxf(m1, fmaxf(accS[ni][2], accS[ni][3]));
    }
#pragma unroll
    for (int o = 1; o <= 2; o <<= 1) {
        m0 = fmaxf(m0, __shfl_xor_sync(0xffffffffu, m0, o));
        m1 = fmaxf(m1, __shfl_xor_sync(0xffffffffu, m1, o));
    }
    float d0 = 0.0f, d1 = 0.0f;
#pragma unroll
    for (int ni = 0; ni < 4; ni++) {
        accS[ni][0] = __expf(accS[ni][0] - m0);
        accS[ni][1] = __expf(accS[ni][1] - m0);
        accS[ni][2] = __expf(accS[ni][2] - m1);
        accS[ni][3] = __expf(accS[ni][3] - m1);
        d0 += accS[ni][0] + accS[ni][1];
        d1 += accS[ni][2] + accS[ni][3];
    }
#pragma unroll
    for (int o = 1; o <= 2; o <<= 1) {
        d0 += __shfl_xor_sync(0xffffffffu, d0, o);
        d1 += __shfl_xor_sync(0xffffffffu, d1, o);
    }
    const float inv0 = 1.0f / d0, inv1 = 1.0f / d1;

    uint32_t aP[2][4];
#pragma unroll
    for (int ks = 0; ks < 2; ks++) {
        __half2 v0 = __floats2half2_rn(accS[2 * ks][0] * inv0,
                                       accS[2 * ks][1] * inv0);
        __half2 v1 = __floats2half2_rn(accS[2 * ks][2] * inv1,
                                       accS[2 * ks][3] * inv1);
        __half2 v2 = __floats2half2_rn(accS[2 * ks + 1][0] * inv0,
                                       accS[2 * ks + 1][1] * inv0);
        __half2 v3 = __floats2half2_rn(accS[2 * ks + 1][2] * inv1,
                                       accS[2 * ks + 1][3] * inv1);
        aP[ks][0] = *(uint32_t*)&v0;
        aP[ks][1] = *(uint32_t*)&v1;
        aP[ks][2] = *(uint32_t*)&v2;
        aP[ks][3] = *(uint32_t*)&v3;
    }

    asm volatile("cp.async.wait_group 0;" ::: "memory");
    __syncthreads();

    float accO[8][4];
#pragma unroll
    for (int i = 0; i < 8; i++)
#pragma unroll
        for (int r = 0; r < 4; r++) accO[i][r] = 0.0f;

#pragma unroll
    for (int g = 0; g < 4; g++)
#pragma unroll
        for (int ks = 0; ks < 2; ks++) {
            uint32_t bv[4];
            ldsm_x4_t(bv, bv_off + ks * 16 * PV + g * 32);
            mma16816(accO[2 * g],     aP[ks], &bv[0]);
            mma16816(accO[2 * g + 1], aP[ks], &bv[2]);
        }

    const int q0 = s0 + 16 * w;
#pragma unroll
    for (int nf = 0; nf < 8; nf++) {
        int col = 8 * nf + 2 * t4;
        __half2 p0 = __floats2half2_rn(accO[nf][0], accO[nf][1]);
        __half2 p1 = __floats2half2_rn(accO[nf][2], accO[nf][3]);
        *(uint32_t*)(O + rowbase + (size_t)(q0 + grp) * HID + col)     = *(uint32_t*)&p0;
        *(uint32_t*)(O + rowbase + (size_t)(q0 + grp + 8) * HID + col) = *(uint32_t*)&p1;
    }
}

// ---------------------------------------------------------------------------
// Launch
// ---------------------------------------------------------------------------
extern "C" void kernel_launch(void* const* d_in, const int* in_sizes, int n_in,
                              void* d_out, int out_size)
{
    const float* hs  = (const float*)d_in[0];
    const float* w_q = (const float*)d_in[1];
    const float* b_q = (const float*)d_in[2];
    const float* w_k = (const float*)d_in[3];
    const float* b_k = (const float*)d_in[4];
    const float* w_v = (const float*)d_in[5];
    const float* b_v = (const float*)d_in[6];
    const float* w_o = (const float*)d_in[7];
    const float* b_o = (const float*)d_in[8];
    float* out = (float*)d_out;

    __half *qb, *kb, *vb, *ab, *wt;
    cudaGetSymbolAddress((void**)&qb, g_q);
    cudaGetSymbolAddress((void**)&kb, g_k);
    cudaGetSymbolAddress((void**)&vb, g_v);
    cudaGetSymbolAddress((void**)&ab, g_a);
    cudaGetSymbolAddress((void**)&wt, g_w);

    cudaFuncSetAttribute(gemm_mma<true>,
                         cudaFuncAttributeMaxDynamicSharedMemorySize, SMEMB);
    cudaFuncSetAttribute(gemm_mma<false>,
                         cudaFuncAttributeMaxDynamicSharedMemorySize, SMEMB);
    cudaFuncSetAttribute(attn_mma,
                         cudaFuncAttributeMaxDynamicSharedMemorySize, ASMEM);

    // 1) fused prep: activation convert + weight transpose (one launch)
    prep_kernel<<<PREP_BLOCKS, 256>>>(hs, ab, w_q, w_k, w_v, w_o, wt);

    // 2) fused QKV GEMM: 3 matrices x 8 N-tiles(128) x 128 M-tiles -> fp16
    gemm_mma<true><<<dim3(24, 128), 256, SMEMB>>>(
        ab, wt, 0, b_q, b_k, b_v, qb, kb, vb);

    // 3) HMMA neighborhood attention (fp16 in, fp16 out into A operand)
    attn_mma<<<BATCH * NHEADS * (SEQ / 128), 256, ASMEM>>>(qb, kb, vb, ab);

    // 4) O projection -> fp32 output
    gemm_mma<false><<<dim3(8, 128), 256, SMEMB>>>(
        ab, wt, 3, b_o, b_o, b_o, out, out, out);
}

// round 14
// speedup vs baseline: 3.2278x; 1.1914x over previous
#include <cuda_runtime.h>
#include <cuda_fp16.h>
#include <math.h>
#include <stdint.h>

// ---------------------------------------------------------------------------
// Problem constants
// ---------------------------------------------------------------------------
#define BATCH     2
#define SEQ       8192
#define HID       1024
#define NHEADS    16
#define HDIM      64
#define KWIN      7
#define ATT_SCALE 0.125f
#define M_ROWS    (BATCH * SEQ)     // 16384

// ---------------------------------------------------------------------------
// Scratch (__device__ globals: allowed, no runtime allocation)
// ---------------------------------------------------------------------------
__device__ __half g_q[(size_t)M_ROWS * HID];
__device__ __half g_k[(size_t)M_ROWS * HID];
__device__ __half g_v[(size_t)M_ROWS * HID];
__device__ __half g_a[(size_t)M_ROWS * HID];      // fp16 A operand (reused)
__device__ __half g_w[(size_t)4 * HID * HID];     // transposed [n][k], fp16

// ---------------------------------------------------------------------------
// PTX helpers (base sm_103 target — NO 'a'-gated features)
// ---------------------------------------------------------------------------
__device__ __forceinline__ uint32_t smem_u32(const void* p) {
    uint32_t a;
    asm("{ .reg .u64 t; cvta.to.shared.u64 t, %1; cvt.u32.u64 %0, t; }"
        : "=r"(a) : "l"(p));
    return a;
}
__device__ __forceinline__ void cp16(uint32_t s, const void* g) {
    asm volatile("cp.async.cg.shared.global [%0], [%1], 16;"
                 :: "r"(s), "l"(g));
}
__device__ __forceinline__ void ldsm_x4(uint32_t* r, uint32_t addr) {
    asm volatile("ldmatrix.sync.aligned.m8n8.x4.shared.b16 {%0,%1,%2,%3}, [%4];"
                 : "=r"(r[0]), "=r"(r[1]), "=r"(r[2]), "=r"(r[3]) : "r"(addr));
}
__device__ __forceinline__ void ldsm_x4_t(uint32_t* r, uint32_t addr) {
    asm volatile("ldmatrix.sync.aligned.m8n8.x4.trans.shared.b16 {%0,%1,%2,%3}, [%4];"
                 : "=r"(r[0]), "=r"(r[1]), "=r"(r[2]), "=r"(r[3]) : "r"(addr));
}
__device__ __forceinline__ void mma16816(float* d, const uint32_t* a,
                                         const uint32_t* b) {
    asm volatile(
        "mma.sync.aligned.m16n8k16.row.col.f32.f16.f16.f32 "
        "{%0,%1,%2,%3}, {%4,%5,%6,%7}, {%8,%9}, {%0,%1,%2,%3};"
        : "+f"(d[0]), "+f"(d[1]), "+f"(d[2]), "+f"(d[3])
        : "r"(a[0]), "r"(a[1]), "r"(a[2]), "r"(a[3]), "r"(b[0]), "r"(b[1]));
}

// ---------------------------------------------------------------------------
// GEMM config: 128x128 CTA tile, BK=32, 4-stage cp.async ring, 128 threads
// (4 warps, 2x2 grid of 64x64 warp tiles), 2 CTAs per SM.
// 64x64 warp tile: 16 ldsm per 64 MMAs -> 1.5x less smem-read per MMA.
// ---------------------------------------------------------------------------
#define PITCH   80
#define TILE_A  (128 * PITCH)           // 10240
#define OFF_B   TILE_A
#define BUFB    (2 * TILE_A)            // 20480 per stage (A + B)
#define NSTAGE  4
#define SMEMB   (NSTAGE * BUFB)         // 81920

__device__ __forceinline__ void load_chunk(
    uint32_t base, int tid, int k0, int m0, int n0,
    const __half* __restrict__ A, const __half* __restrict__ B)
{
#pragma unroll
    for (int r = 0; r < 4; r++) {   // A: 128 rows x 64B = 512 cp16
        int idx = tid + r * 128;
        int row = idx >> 2, c = idx & 3;
        uint32_t so = (uint32_t)(row * PITCH + c * 16);
        size_t go = (size_t)(m0 + row) * HID + k0 + c * 8;
        cp16(base + so, A + go);
    }
#pragma unroll
    for (int r = 0; r < 4; r++) {   // B: 128 rows x 64B = 512 cp16
        int idx = tid + r * 128;
        int row = idx >> 2, c = idx & 3;
        uint32_t so = (uint32_t)(row * PITCH + c * 16);
        size_t go = (size_t)(n0 + row) * HID + k0 + c * 8;
        cp16(base + OFF_B + so, B + go);
    }
    asm volatile("cp.async.commit_group;" ::: "memory");
}

// C[m][n] = sum_k A[m][k]*Wt[n][k] + bias[n], single-pass fp16 HMMA.
// grid.x: (matrix_within_launch << 3) | n_tile;  grid.y: m_tile
template <bool HALF_OUT>
__global__ void __launch_bounds__(128, 2)
gemm_mma(const __half* __restrict__ A, const __half* __restrict__ W,
         int mat_base,
         const float* __restrict__ bias0, const float* __restrict__ bias1,
         const float* __restrict__ bias2,
         void* __restrict__ c0v, void* __restrict__ c1v, void* __restrict__ c2v)
{
    extern __shared__ char smem[];
    const uint32_t sb = smem_u32(smem);
    const int tid  = threadIdx.x;
    const int lane = tid & 31;
    const int wid  = tid >> 5;          // 0..3
    const int wm   = wid >> 1;          // 0..1 -> 64-row slab
    const int wn   = wid & 1;           // 0..1 -> 64-col slab
    const int mi_  = blockIdx.x >> 3;   // matrix within launch
    const int n0   = (blockIdx.x & 7) * 128;
    const int m0   = blockIdx.y * 128;

    const __half* B = W + (size_t)(mat_base + mi_) * HID * HID;
    const float* bias = (mi_ == 0) ? bias0 : ((mi_ == 1) ? bias1 : bias2);
    void* Cv = (mi_ == 0) ? c0v : ((mi_ == 1) ? c1v : c2v);

    float acc[4][8][4];                 // 64x64 warp tile: mi x ni x frag
#pragma unroll
    for (int i = 0; i < 4; i++)
#pragma unroll
        for (int j = 0; j < 8; j++)
#pragma unroll
            for (int r = 0; r < 4; r++) acc[i][j][r] = 0.0f;

    load_chunk(sb,            tid, 0,  m0, n0, A, B);
    load_chunk(sb + BUFB,     tid, 32, m0, n0, A, B);
    load_chunk(sb + 2 * BUFB, tid, 64, m0, n0, A, B);

    const int mrow = lane >> 3;
    const int jrow = lane & 7;
    const uint32_t a_off = (uint32_t)((wm * 64 + (mrow & 1) * 8 + jrow) * PITCH
                                      + (mrow >> 1) * 16);
    const uint32_t b_off = (uint32_t)((wn * 64 + (mrow >> 1) * 8 + jrow) * PITCH
                                      + (mrow & 1) * 16) + OFF_B;

    const int NCHUNK = HID / 32;        // 32
    int st = 0;

    for (int ck = 0; ck < NCHUNK; ck++) {
        if (ck <= NCHUNK - 3)      asm volatile("cp.async.wait_group 2;" ::: "memory");
        else if (ck == NCHUNK - 2) asm volatile("cp.async.wait_group 1;" ::: "memory");
        else                       asm volatile("cp.async.wait_group 0;" ::: "memory");
        __syncthreads();

        if (ck + 3 < NCHUNK) {
            int ls = st + 3; if (ls >= NSTAGE) ls -= NSTAGE;
            load_chunk(sb + ls * BUFB, tid, (ck + 3) * 32, m0, n0, A, B);
        }

        const uint32_t base = sb + st * BUFB;
#pragma unroll
        for (int ks = 0; ks < 2; ks++) {
            const uint32_t kb = ks * 32;
            uint32_t bf[4][4];          // 64 cols = 4 x ldsm.x4
#pragma unroll
            for (int nj = 0; nj < 4; nj++)
                ldsm_x4(bf[nj], base + b_off + nj * 16 * PITCH + kb);
#pragma unroll
            for (int mi = 0; mi < 4; mi++) {
                uint32_t ah[4];
                ldsm_x4(ah, base + a_off + mi * 16 * PITCH + kb);
#pragma unroll
                for (int ni = 0; ni < 8; ni++)
                    mma16816(acc[mi][ni], ah, &bf[ni >> 1][(ni & 1) * 2]);
            }
        }
        if (++st == NSTAGE) st = 0;
    }

    const int grp = lane >> 2, t4 = lane & 3;
#pragma unroll
    for (int ni = 0; ni < 8; ni++) {
        const int col = n0 + wn * 64 + ni * 8 + t4 * 2;
        const float bv0 = bias[col], bv1 = bias[col + 1];
#pragma unroll
        for (int mi = 0; mi < 4; mi++) {
            const int r0 = m0 + wm * 64 + mi * 16 + grp;
            if (HALF_OUT) {
                __half* C = (__half*)Cv;
                __half2 p0 = __floats2half2_rn(acc[mi][ni][0] + bv0,
                                               acc[mi][ni][1] + bv1);
                __half2 p1 = __floats2half2_rn(acc[mi][ni][2] + bv0,
                                               acc[mi][ni][3] + bv1);
                *(uint32_t*)(C + (size_t)r0 * HID + col)       = *(uint32_t*)&p0;
                *(uint32_t*)(C + (size_t)(r0 + 8) * HID + col) = *(uint32_t*)&p1;
            } else {
                float* C = (float*)Cv;
                *(float2*)(C + (size_t)r0 * HID + col) =
                    make_float2(acc[mi][ni][0] + bv0, acc[mi][ni][1] + bv1);
                *(float2*)(C + (size_t)(r0 + 8) * HID + col) =
                    make_float2(acc[mi][ni][2] + bv0, acc[mi][ni][3] + bv1);
            }
        }
    }
}

// ---------------------------------------------------------------------------
// Fused prep: blocks [0,16384) convert activations fp32->fp16;
// blocks [16384,20480) transpose+round the 4 weight matrices.
// ---------------------------------------------------------------------------
#define CONV_BLOCKS 16384
#define PREP_BLOCKS (CONV_BLOCKS + 4096)

__global__ void __launch_bounds__(256)
prep_kernel(const float* __restrict__ x, __half* __restrict__ y,
            const float* __restrict__ w0, const float* __restrict__ w1,
            const float* __restrict__ w2, const float* __restrict__ w3,
            __half* __restrict__ wt)
{
    __shared__ float t[32][33];
    if (blockIdx.x < CONV_BLOCKS) {
        size_t i = ((size_t)blockIdx.x * 256 + threadIdx.x) * 4;
        float4 v = *(const float4*)(x + i);
        __half2 p0 = __floats2half2_rn(v.x, v.y);
        __half2 p1 = __floats2half2_rn(v.z, v.w);
        *(uint2*)(y + i) = make_uint2(*(uint32_t*)&p0, *(uint32_t*)&p1);
    } else {
        const int bid = blockIdx.x - CONV_BLOCKS;
        const int z = bid >> 10;
        const int rem = bid & 1023;
        const int n0 = (rem & 31) * 32, k0 = (rem >> 5) * 32;
        const float* W = (z == 0) ? w0 : ((z == 1) ? w1 : ((z == 2) ? w2 : w3));
        const int tx = threadIdx.x & 31, ty = threadIdx.x >> 5;
#pragma unroll
        for (int r = 0; r < 4; r++)
            t[ty + r * 8][tx] = W[(size_t)(k0 + ty + r * 8) * HID + n0 + tx];
        __syncthreads();
        const size_t base = (size_t)z * HID * HID;
#pragma unroll
        for (int r = 0; r < 4; r++) {
            int n = n0 + ty + r * 8;
            int k = k0 + tx;
            wt[base + (size_t)n * HID + k] = __float2half_rn(t[tx][ty + r * 8]);
        }
    }
}

// ---------------------------------------------------------------------------
// HMMA neighborhood attention (two-group staging; unchanged from R12/R13)
// ---------------------------------------------------------------------------
#define PV      144
#define ASMEM   ((128 + 144 + 144) * PV)    // 59904

__global__ void __launch_bounds__(256)
attn_mma(const __half* __restrict__ Q, const __half* __restrict__ K,
         const __half* __restrict__ V, __half* __restrict__ O)
{
    extern __shared__ char smem[];
    const uint32_t sbq = smem_u32(smem);
    const uint32_t sbk = sbq + 128 * PV;
    const uint32_t sbv = sbk + 144 * PV;
    const int tid = threadIdx.x, lane = tid & 31, w = tid >> 5;
    const int bh = blockIdx.x >> 6;
    const int s0 = (blockIdx.x & 63) * 128;
    const int b = bh >> 4, h = bh & 15;
    const size_t rowbase = ((size_t)b * SEQ) * HID + h * HDIM;

#pragma unroll
    for (int r = 0; r < 4; r++) {
        int idx = tid + r * 256;
        int row = idx >> 3, c = idx & 7;
        cp16(sbq + row * PV + c * 16,
             Q + rowbase + (size_t)(s0 + row) * HID + c * 8);
    }
    for (int idx = tid; idx < 1152; idx += 256) {
        int row = idx >> 3, c = idx & 7;
        int sk = s0 + row - 3;
        sk = sk < 0 ? 0 : (sk >= SEQ ? SEQ - 1 : sk);
        cp16(sbk + row * PV + c * 16, K + rowbase + (size_t)sk * HID + c * 8);
    }
    asm volatile("cp.async.commit_group;" ::: "memory");
    for (int idx = tid; idx < 1152; idx += 256) {
        int row = idx >> 3, c = idx & 7;
        int sk = s0 + row - 3;
        sk = sk < 0 ? 0 : (sk >= SEQ ? SEQ - 1 : sk);
        cp16(sbv + row * PV + c * 16, V + rowbase + (size_t)sk * HID + c * 8);
    }
    asm volatile("cp.async.commit_group;" ::: "memory");
    asm volatile("cp.async.wait_group 1;" ::: "memory");
    __syncthreads();

    const int mrow = lane >> 3, jrow = lane & 7;
    const int grp = lane >> 2, t4 = lane & 3;
    const uint32_t aq_off = sbq + (uint32_t)((w * 16 + (mrow & 1) * 8 + jrow) * PV
                                             + (mrow >> 1) * 16);
    const uint32_t bk_off = sbk + (uint32_t)((w * 16 + (mrow >> 1) * 8 + jrow) * PV
                                             + (mrow & 1) * 16);
    const uint32_t bv_off = sbv + (uint32_t)((w * 16 + (mrow & 1) * 8 + jrow) * PV
                                             + (mrow >> 1) * 16);

    float accS[4][4];
#pragma unroll
    for (int i = 0; i < 4; i++)
#pragma unroll
        for (int r = 0; r < 4; r++) accS[i][r] = 0.0f;

#pragma unroll
    for (int ks = 0; ks < 4; ks++) {
        uint32_t aq[4], bk0[4], bk1[4];
        ldsm_x4(aq,  aq_off + ks * 32);
        ldsm_x4(bk0, bk_off + ks * 32);
        ldsm_x4(bk1, bk_off + 16 * PV + ks * 32);
        mma16816(accS[0], aq, &bk0[0]);
        mma16816(accS[1], aq, &bk0[2]);
        mma16816(accS[2], aq, &bk1[0]);
        mma16816(accS[3], aq, &bk1[2]);
    }

    const float NEG = -1e30f;
#pragma unroll
    for (int ni = 0; ni < 4; ni++)
#pragma unroll
        for (int pp = 0; pp < 4; pp++) {
            int r = (pp >= 2) ? grp + 8 : grp;
            int c = 8 * ni + 2 * t4 + (pp & 1);
            int sk = s0 + 16 * w + c - 3;
            bool ok = (c >= r) && (c <= r + 6) && (sk >= 0) && (sk < SEQ);
            accS[ni][pp] = ok ? accS[ni][pp] * ATT_SCALE : NEG;
        }

    float m0 = NEG, m1 = NEG;
#pragma unroll
    for (int ni = 0; ni < 4; ni++) {
        m0 = fmaxf(m0, fmaxf(accS[ni][0], accS[ni][1]));
        m1 = fmaxf(m1, fmaxf(accS[ni][2], accS[ni][3]));
    }
#pragma unroll
    for (int o = 1; o <= 2; o <<= 1) {
        m0 = fmaxf(m0, __shfl_xor_sync(0xffffffffu, m0, o));
        m1 = fmaxf(m1, __shfl_xor_sync(0xffffffffu, m1, o));
    }
    float d0 = 0.0f, d1 = 0.0f;
#pragma unroll
    for (int ni = 0; ni < 4; ni++) {
        accS[ni][0] = __expf(accS[ni][0] - m0);
        accS[ni][1] = __expf(accS[ni][1] - m0);
        accS[ni][2] = __expf(accS[ni][2] - m1);
        accS[ni][3] = __expf(accS[ni][3] - m1);
        d0 += accS[ni][0] + accS[ni][1];
        d1 += accS[ni][2] + accS[ni][3];
    }
#pragma unroll
    for (int o = 1; o <= 2; o <<= 1) {
        d0 += __shfl_xor_sync(0xffffffffu, d0, o);
        d1 += __shfl_xor_sync(0xffffffffu, d1, o);
    }
    const float inv0 = 1.0f / d0, inv1 = 1.0f / d1;

    uint32_t aP[2][4];
#pragma unroll
    for (int ks = 0; ks < 2; ks++) {
        __half2 v0 = __floats2half2_rn(accS[2 * ks][0] * inv0,
                                       accS[2 * ks][1] * inv0);
        __half2 v1 = __floats2half2_rn(accS[2 * ks][2] * inv1,
                                       accS[2 * ks][3] * inv1);
        __half2 v2 = __floats2half2_rn(accS[2 * ks + 1][0] * inv0,
                                       accS[2 * ks + 1][1] * inv0);
        __half2 v3 = __floats2half2_rn(accS[2 * ks + 1][2] * inv1,
                                       accS[2 * ks + 1][3] * inv1);
        aP[ks][0] = *(uint32_t*)&v0;
        aP[ks][1] = *(uint32_t*)&v1;
        aP[ks][2] = *(uint32_t*)&v2;
        aP[ks][3] = *(uint32_t*)&v3;
    }

    asm volatile("cp.async.wait_group 0;" ::: "memory");
    __syncthreads();

    float accO[8][4];
#pragma unroll
    for (int i = 0; i < 8; i++)
#pragma unroll
        for (int r = 0; r < 4; r++) accO[i][r] = 0.0f;

#pragma unroll
    for (int g = 0; g < 4; g++)
#pragma unroll
        for (int ks = 0; ks < 2; ks++) {
            uint32_t bv[4];
            ldsm_x4_t(bv, bv_off + ks * 16 * PV + g * 32);
            mma16816(accO[2 * g],     aP[ks], &bv[0]);
            mma16816(accO[2 * g + 1], aP[ks], &bv[2]);
        }

    const int q0 = s0 + 16 * w;
#pragma unroll
    for (int nf = 0; nf < 8; nf++) {
        int col = 8 * nf + 2 * t4;
        __half2 p0 = __floats2half2_rn(accO[nf][0], accO[nf][1]);
        __half2 p1 = __floats2half2_rn(accO[nf][2], accO[nf][3]);
        *(uint32_t*)(O + rowbase + (size_t)(q0 + grp) * HID + col)     = *(uint32_t*)&p0;
        *(uint32_t*)(O + rowbase + (size_t)(q0 + grp + 8) * HID + col) = *(uint32_t*)&p1;
    }
}

// ---------------------------------------------------------------------------
// Launch
// ---------------------------------------------------------------------------
extern "C" void kernel_launch(void* const* d_in, const int* in_sizes, int n_in,
                              void* d_out, int out_size)
{
    const float* hs  = (const float*)d_in[0];
    const float* w_q = (const float*)d_in[1];
    const float* b_q = (const float*)d_in[2];
    const float* w_k = (const float*)d_in[3];
    const float* b_k = (const float*)d_in[4];
    const float* w_v = (const float*)d_in[5];
    const float* b_v = (const float*)d_in[6];
    const float* w_o = (const float*)d_in[7];
    const float* b_o = (const float*)d_in[8];
    float* out = (float*)d_out;

    __half *qb, *kb, *vb, *ab, *wt;
    cudaGetSymbolAddress((void**)&qb, g_q);
    cudaGetSymbolAddress((void**)&kb, g_k);
    cudaGetSymbolAddress((void**)&vb, g_v);
    cudaGetSymbolAddress((void**)&ab, g_a);
    cudaGetSymbolAddress((void**)&wt, g_w);

    cudaFuncSetAttribute(gemm_mma<true>,
                         cudaFuncAttributeMaxDynamicSharedMemorySize, SMEMB);
    cudaFuncSetAttribute(gemm_mma<false>,
                         cudaFuncAttributeMaxDynamicSharedMemorySize, SMEMB);
    cudaFuncSetAttribute(attn_mma,
                         cudaFuncAttributeMaxDynamicSharedMemorySize, ASMEM);

    // 1) fused prep: activation convert + weight transpose (one launch)
    prep_kernel<<<PREP_BLOCKS, 256>>>(hs, ab, w_q, w_k, w_v, w_o, wt);

    // 2) fused QKV GEMM: 3 matrices x 8 N-tiles(128) x 128 M-tiles -> fp16
    gemm_mma<true><<<dim3(24, 128), 128, SMEMB>>>(
        ab, wt, 0, b_q, b_k, b_v, qb, kb, vb);

    // 3) HMMA neighborhood attention (fp16 in, fp16 out into A operand)
    attn_mma<<<BATCH * NHEADS * (SEQ / 128), 256, ASMEM>>>(qb, kb, vb, ab);

    // 4) O projection -> fp32 output
    gemm_mma<false><<<dim3(8, 128), 128, SMEMB>>>(
        ab, wt, 3, b_o, b_o, b_o, out, out, out);
}